// round 5
// baseline (speedup 1.0000x reference)
#include <cuda_runtime.h>

#define N_NODES 100000
#define N_EDGES 1600000
#define SCAN_BLOCKS 98   // ceil(100000/1024)

typedef unsigned long long ull;

// ---------------- scratch (static __device__ allocations; no cudaMalloc) ----
__device__ float g_y[(size_t)N_NODES * 128];   // (A@W)*dinv buffer
__device__ float g_h[(size_t)N_NODES * 128];   // post-aggregate hidden buffer
__device__ int   g_cnt[N_NODES];
__device__ int   g_rowptr[N_NODES + 1];
__device__ int   g_cursor[N_NODES];
__device__ float g_dinv[N_NODES];
__device__ int   g_csr[N_EDGES];
__device__ int   g_bsums[SCAN_BLOCKS];
__device__ int   g_is64;

// ---------------- helpers ---------------------------------------------------
__device__ __forceinline__ float4 f4add(float4 a, float4 b) {
    return make_float4(a.x + b.x, a.y + b.y, a.z + b.z, a.w + b.w);
}

// packed f32x2 FMA: d = a*b + d (lane-wise on the two packed floats)
__device__ __forceinline__ void ffma2(ull& d, ull a, ull b) {
    asm("fma.rn.f32x2 %0, %1, %2, %0;" : "+l"(d) : "l"(a), "l"(b));
}
__device__ __forceinline__ ull pack2(float lo, float hi) {
    ull r;
    asm("mov.b64 %0, {%1, %2};" : "=l"(r) : "f"(lo), "f"(hi));
    return r;
}
__device__ __forceinline__ float2 unpack2(ull v) {
    float lo, hi;
    asm("mov.b64 {%0, %1}, %2;" : "=f"(lo), "=f"(hi) : "l"(v));
    return make_float2(lo, hi);
}

// Fetch (src, dst) of edge e, supporting int32 (expected) or int64 layout.
__device__ __forceinline__ void edge_fetch(const int* __restrict__ ei, int e,
                                           int& src, int& dst, int is64) {
    if (is64) {
        src = ei[2 * e];
        dst = ei[2 * (N_EDGES + e)];
    } else {
        src = ei[e];
        dst = ei[N_EDGES + e];
    }
}

// ---------------- dtype detection -------------------------------------------
__global__ void k_detect(const int* __restrict__ ei) {
    if (threadIdx.x == 0) {
        int acc = 0;
        for (int i = 0; i < 64; i++) acc |= ei[2 * i + 1];
        g_is64 = (acc == 0) ? 1 : 0;
    }
}

// ---------------- CSR construction ------------------------------------------
__global__ void k_init() {
    int i = blockIdx.x * blockDim.x + threadIdx.x;
    if (i < N_NODES) g_cnt[i] = 0;
}

__global__ void k_hist(const int* __restrict__ ei) {
    int e = blockIdx.x * blockDim.x + threadIdx.x;
    if (e < N_EDGES) {
        int src, dst;
        edge_fetch(ei, e, src, dst, g_is64);
        if ((unsigned)dst < N_NODES) atomicAdd(&g_cnt[dst], 1);
    }
}

__global__ void k_scan1() {
    __shared__ int sm[1024];
    int i = blockIdx.x * 1024 + threadIdx.x;
    int v = (i < N_NODES) ? g_cnt[i] : 0;
    sm[threadIdx.x] = v;
    __syncthreads();
#pragma unroll
    for (int off = 1; off < 1024; off <<= 1) {
        int t = (threadIdx.x >= off) ? sm[threadIdx.x - off] : 0;
        __syncthreads();
        sm[threadIdx.x] += t;
        __syncthreads();
    }
    int incl = sm[threadIdx.x];
    if (i < N_NODES) g_rowptr[i] = incl - v;     // block-local exclusive
    if (threadIdx.x == 1023) g_bsums[blockIdx.x] = incl;
}

__global__ void k_scan2() {
    if (threadIdx.x == 0) {
        int run = 0;
        for (int b = 0; b < SCAN_BLOCKS; b++) {
            int v = g_bsums[b];
            g_bsums[b] = run;
            run += v;
        }
    }
}

__global__ void k_scan3() {
    int i = blockIdx.x * 1024 + threadIdx.x;
    if (i < N_NODES) {
        int rp = g_rowptr[i] + g_bsums[blockIdx.x];
        g_rowptr[i] = rp;
        g_cursor[i] = rp;
        g_dinv[i] = rsqrtf((float)(g_cnt[i] + 1));  // +1 self-loop
    }
    if (i == 0) g_rowptr[N_NODES] = N_EDGES;
}

__global__ void k_fill(const int* __restrict__ ei) {
    int e = blockIdx.x * blockDim.x + threadIdx.x;
    if (e < N_EDGES) {
        int src, dst;
        edge_fetch(ei, e, src, dst, g_is64);
        if ((unsigned)dst < N_NODES && (unsigned)src < N_NODES) {
            int pos = atomicAdd(&g_cursor[dst], 1);
            g_csr[pos] = src;
        }
    }
}

// ---------------- GEMM (FFMA2): out[row][c] = sum_k A[row][k]*W[k][c] -------
// 256 threads/block, 8 warps, warp handles 8 rows, lane handles 4 cols.
// Packed over K: acc2[r][c] holds (even-k partial, odd-k partial); A pairs
// come free from the float4 row load; W pairs packed once per chunk (x8 rows reuse).
// SRC: 0 = A param, 1 = g_h. MODE: 0 = *dinv -> g_y; 1 = FC head -> q.
template <int SRC, int MODE, int KCH>
__global__ void __launch_bounds__(256) k_gemm(
    const float* __restrict__ A, const float* __restrict__ A2,
    const float* __restrict__ W,
    const float* __restrict__ bias, const float* __restrict__ w2,
    const float* __restrict__ w2b, float* __restrict__ out)
{
    const int lane = threadIdx.x & 31;
    const int warp = threadIdx.x >> 5;
    const int row0 = (blockIdx.x * 8 + warp) * 8;
    const int c4 = lane * 4;

    const float* __restrict__ Abase = (SRC == 0) ? A : (const float*)g_h;

    int rc[8];
#pragma unroll
    for (int r = 0; r < 8; r++) {
        int row = row0 + r;
        rc[r] = (row < N_NODES) ? row : (N_NODES - 1);
    }

    ull acc[8][4];
#pragma unroll
    for (int r = 0; r < 8; r++)
#pragma unroll
        for (int c = 0; c < 4; c++) acc[r][c] = 0ull;

#pragma unroll 2
    for (int kc = 0; kc < KCH; kc++) {
        const int k = kc * 4;
        float4 w0 = __ldg((const float4*)(W + (size_t)(k + 0) * 128 + c4));
        float4 w1 = __ldg((const float4*)(W + (size_t)(k + 1) * 128 + c4));
        float4 w2v = __ldg((const float4*)(W + (size_t)(k + 2) * 128 + c4));
        float4 w3 = __ldg((const float4*)(W + (size_t)(k + 3) * 128 + c4));
        // k-pair packed weights: wp0[c] = (w[k][c], w[k+1][c]); wp1[c] = (w[k+2][c], w[k+3][c])
        ull wp0[4], wp1[4];
        wp0[0] = pack2(w0.x, w1.x); wp1[0] = pack2(w2v.x, w3.x);
        wp0[1] = pack2(w0.y, w1.y); wp1[1] = pack2(w2v.y, w3.y);
        wp0[2] = pack2(w0.z, w1.z); wp1[2] = pack2(w2v.z, w3.z);
        wp0[3] = pack2(w0.w, w1.w); wp1[3] = pack2(w2v.w, w3.w);
#pragma unroll
        for (int r = 0; r < 8; r++) {
            float4 av;
            if (MODE == 1) {
                if (k < 128)
                    av = __ldg((const float4*)(Abase + (size_t)rc[r] * 128 + k));
                else
                    av = __ldg((const float4*)(A2 + (size_t)rc[r] * 16 + (k - 128)));
            } else {
                av = __ldg((const float4*)(Abase + (size_t)rc[r] * 128 + k));
            }
            ulonglong2 ap = *reinterpret_cast<ulonglong2*>(&av);  // (a[k],a[k+1]),(a[k+2],a[k+3])
#pragma unroll
            for (int c = 0; c < 4; c++) {
                ffma2(acc[r][c], ap.x, wp0[c]);
                ffma2(acc[r][c], ap.y, wp1[c]);
            }
        }
    }

    if (MODE == 0) {
#pragma unroll
        for (int r = 0; r < 8; r++) {
            int row = row0 + r;
            if (row < N_NODES) {
                float s = g_dinv[row];
                float2 p0 = unpack2(acc[r][0]);
                float2 p1 = unpack2(acc[r][1]);
                float2 p2 = unpack2(acc[r][2]);
                float2 p3 = unpack2(acc[r][3]);
                float4 o = make_float4((p0.x + p0.y) * s, (p1.x + p1.y) * s,
                                       (p2.x + p2.y) * s, (p3.x + p3.y) * s);
                *(float4*)(g_y + (size_t)row * 128 + c4) = o;
            }
        }
    } else {
        float4 b4 = __ldg((const float4*)(bias + c4));
        float4 wv = __ldg((const float4*)(w2 + c4));
        float ob = __ldg(w2b);
#pragma unroll
        for (int r = 0; r < 8; r++) {
            float2 p0 = unpack2(acc[r][0]);
            float2 p1 = unpack2(acc[r][1]);
            float2 p2 = unpack2(acc[r][2]);
            float2 p3 = unpack2(acc[r][3]);
            float hx = fmaxf(p0.x + p0.y + b4.x, 0.f);
            float hy = fmaxf(p1.x + p1.y + b4.y, 0.f);
            float hz = fmaxf(p2.x + p2.y + b4.z, 0.f);
            float hw = fmaxf(p3.x + p3.y + b4.w, 0.f);
            float p = hx * wv.x + hy * wv.y + hz * wv.z + hw * wv.w;
            p += __shfl_xor_sync(0xFFFFFFFFu, p, 16);
            p += __shfl_xor_sync(0xFFFFFFFFu, p, 8);
            p += __shfl_xor_sync(0xFFFFFFFFu, p, 4);
            p += __shfl_xor_sync(0xFFFFFFFFu, p, 2);
            p += __shfl_xor_sync(0xFFFFFFFFu, p, 1);
            int row = row0 + r;
            if (lane == 0 && row < N_NODES) out[row] = p + ob;
        }
    }
}

// ---------------- gather-aggregate: one warp per dst row --------------------
// g_h[i][c] = relu( dinv[i] * ( g_y[i][c] + sum_{src in in(i)} g_y[src][c] ) + b[c] )
__global__ void __launch_bounds__(256) k_aggregate(
    const float* __restrict__ bias)
{
    const int lane = threadIdx.x & 31;
    const int warp = threadIdx.x >> 5;
    const int row = blockIdx.x * 8 + warp;
    if (row >= N_NODES) return;

    const int s = g_rowptr[row];
    const int e = g_rowptr[row + 1];
    const float4* yv = (const float4*)g_y;

    float4 a0 = __ldg(&yv[(size_t)row * 32 + lane]);  // self-loop term
    float4 a1 = make_float4(0.f, 0.f, 0.f, 0.f);
    float4 a2 = a1, a3 = a1;

    int i = s;
    for (; i + 4 <= e; i += 4) {
        int i0 = g_csr[i + 0];
        int i1 = g_csr[i + 1];
        int i2 = g_csr[i + 2];
        int i3 = g_csr[i + 3];
        a0 = f4add(a0, __ldg(&yv[(size_t)i0 * 32 + lane]));
        a1 = f4add(a1, __ldg(&yv[(size_t)i1 * 32 + lane]));
        a2 = f4add(a2, __ldg(&yv[(size_t)i2 * 32 + lane]));
        a3 = f4add(a3, __ldg(&yv[(size_t)i3 * 32 + lane]));
    }
    for (; i < e; i++) {
        int ix = g_csr[i];
        a0 = f4add(a0, __ldg(&yv[(size_t)ix * 32 + lane]));
    }
    float4 a = f4add(f4add(a0, a1), f4add(a2, a3));

    const float d = g_dinv[row];
    float4 b4 = __ldg((const float4*)(bias + lane * 4));
    float4 o = make_float4(fmaxf(a.x * d + b4.x, 0.f),
                           fmaxf(a.y * d + b4.y, 0.f),
                           fmaxf(a.z * d + b4.z, 0.f),
                           fmaxf(a.w * d + b4.w, 0.f));
    *(float4*)(g_h + (size_t)row * 128 + lane * 4) = o;
}

// ---------------- launch ----------------------------------------------------
extern "C" void kernel_launch(void* const* d_in, const int* in_sizes, int n_in,
                              void* d_out, int out_size)
{
    const float* x      = (const float*)d_in[0];
    const int*   ei     = (const int*)d_in[1];   // int32 (JAX x64 off); detect guards int64
    const float* action = (const float*)d_in[2];
    const float* g1w    = (const float*)d_in[3];
    const float* g1b    = (const float*)d_in[4];
    const float* g2w    = (const float*)d_in[5];
    const float* g2b    = (const float*)d_in[6];
    const float* f1w    = (const float*)d_in[7];
    const float* f1b    = (const float*)d_in[8];
    const float* f2w    = (const float*)d_in[9];
    const float* f2b    = (const float*)d_in[10];
    float*       q      = (float*)d_out;

    const int gemm_grid = (N_NODES + 63) / 64;
    const int agg_grid  = (N_NODES + 7) / 8;

    // CSR build + dinv
    k_detect<<<1, 32>>>(ei);
    k_init<<<(N_NODES + 1023) / 1024, 1024>>>();
    k_hist<<<(N_EDGES + 255) / 256, 256>>>(ei);
    k_scan1<<<SCAN_BLOCKS, 1024>>>();
    k_scan2<<<1, 32>>>();
    k_scan3<<<SCAN_BLOCKS, 1024>>>();
    k_fill<<<(N_EDGES + 255) / 256, 256>>>(ei);

    // Layer 1: g_y = (x @ W1) * dinv ; g_h = relu(dinv*(y_self + sum y[src]) + b1)
    k_gemm<0, 0, 32><<<gemm_grid, 256>>>(x, nullptr, g1w, nullptr, nullptr, nullptr, nullptr);
    k_aggregate<<<agg_grid, 256>>>(g1b);

    // Layer 2: g_y = (g_h @ W2) * dinv ; g_h = relu(...)
    k_gemm<1, 0, 32><<<gemm_grid, 256>>>(nullptr, nullptr, g2w, nullptr, nullptr, nullptr, nullptr);
    k_aggregate<<<agg_grid, 256>>>(g2b);

    // FC head: relu([g_h|action] @ fc1 + b) . fc2 + b2  (fused)
    k_gemm<1, 1, 36><<<gemm_grid, 256>>>(nullptr, action, f1w, f1b, f2w, f2b, q);
}

// round 6
// speedup vs baseline: 1.6626x; 1.6626x over previous
#include <cuda_runtime.h>

#define N_NODES 100000
#define N_EDGES 1600000
#define SCAN_BLOCKS 98   // ceil(100000/1024)
#define TC_WARPS 12500   // (100000/32 row stripes) * (128/32 col tiles)

// ---------------- scratch (static __device__ allocations; no cudaMalloc) ----
__device__ float g_y[(size_t)N_NODES * 128];   // (A@W)*dinv buffer
__device__ float g_h[(size_t)N_NODES * 128];   // post-aggregate hidden buffer
__device__ int   g_cnt[N_NODES];
__device__ int   g_rowptr[N_NODES + 1];
__device__ int   g_cursor[N_NODES];
__device__ float g_dinv[N_NODES];
__device__ int   g_csr[N_EDGES];
__device__ int   g_bsums[SCAN_BLOCKS];
__device__ int   g_is64;

// ---------------- helpers ---------------------------------------------------
__device__ __forceinline__ float4 f4add(float4 a, float4 b) {
    return make_float4(a.x + b.x, a.y + b.y, a.z + b.z, a.w + b.w);
}

__device__ __forceinline__ unsigned to_tf32(float x) {
    unsigned r;
    asm("cvt.rna.tf32.f32 %0, %1;" : "=r"(r) : "f"(x));
    return r;
}

__device__ __forceinline__ void mma_tf32(
    float& d0, float& d1, float& d2, float& d3,
    unsigned a0, unsigned a1, unsigned a2, unsigned a3,
    unsigned b0, unsigned b1)
{
    asm("mma.sync.aligned.m16n8k8.row.col.f32.tf32.tf32.f32 "
        "{%0,%1,%2,%3}, {%4,%5,%6,%7}, {%8,%9}, {%0,%1,%2,%3};"
        : "+f"(d0), "+f"(d1), "+f"(d2), "+f"(d3)
        : "r"(a0), "r"(a1), "r"(a2), "r"(a3), "r"(b0), "r"(b1));
}

// Fetch (src, dst) of edge e, supporting int32 (expected) or int64 layout.
__device__ __forceinline__ void edge_fetch(const int* __restrict__ ei, int e,
                                           int& src, int& dst, int is64) {
    if (is64) {
        src = ei[2 * e];
        dst = ei[2 * (N_EDGES + e)];
    } else {
        src = ei[e];
        dst = ei[N_EDGES + e];
    }
}

// ---------------- dtype detection -------------------------------------------
__global__ void k_detect(const int* __restrict__ ei) {
    if (threadIdx.x == 0) {
        int acc = 0;
        for (int i = 0; i < 64; i++) acc |= ei[2 * i + 1];
        g_is64 = (acc == 0) ? 1 : 0;
    }
}

// ---------------- CSR construction ------------------------------------------
__global__ void k_init() {
    int i = blockIdx.x * blockDim.x + threadIdx.x;
    if (i < N_NODES) g_cnt[i] = 0;
}

__global__ void k_hist(const int* __restrict__ ei) {
    int e = blockIdx.x * blockDim.x + threadIdx.x;
    if (e < N_EDGES) {
        int src, dst;
        edge_fetch(ei, e, src, dst, g_is64);
        if ((unsigned)dst < N_NODES) atomicAdd(&g_cnt[dst], 1);
    }
}

__global__ void k_scan1() {
    __shared__ int sm[1024];
    int i = blockIdx.x * 1024 + threadIdx.x;
    int v = (i < N_NODES) ? g_cnt[i] : 0;
    sm[threadIdx.x] = v;
    __syncthreads();
#pragma unroll
    for (int off = 1; off < 1024; off <<= 1) {
        int t = (threadIdx.x >= off) ? sm[threadIdx.x - off] : 0;
        __syncthreads();
        sm[threadIdx.x] += t;
        __syncthreads();
    }
    int incl = sm[threadIdx.x];
    if (i < N_NODES) g_rowptr[i] = incl - v;     // block-local exclusive
    if (threadIdx.x == 1023) g_bsums[blockIdx.x] = incl;
}

__global__ void k_scan2() {
    if (threadIdx.x == 0) {
        int run = 0;
        for (int b = 0; b < SCAN_BLOCKS; b++) {
            int v = g_bsums[b];
            g_bsums[b] = run;
            run += v;
        }
    }
}

__global__ void k_scan3() {
    int i = blockIdx.x * 1024 + threadIdx.x;
    if (i < N_NODES) {
        int rp = g_rowptr[i] + g_bsums[blockIdx.x];
        g_rowptr[i] = rp;
        g_cursor[i] = rp;
        g_dinv[i] = rsqrtf((float)(g_cnt[i] + 1));  // +1 self-loop
    }
    if (i == 0) g_rowptr[N_NODES] = N_EDGES;
}

__global__ void k_fill(const int* __restrict__ ei) {
    int e = blockIdx.x * blockDim.x + threadIdx.x;
    if (e < N_EDGES) {
        int src, dst;
        edge_fetch(ei, e, src, dst, g_is64);
        if ((unsigned)dst < N_NODES && (unsigned)src < N_NODES) {
            int pos = atomicAdd(&g_cursor[dst], 1);
            g_csr[pos] = src;
        }
    }
}

// ---------------- tf32 tensor-core GEMM: g_y = (A @ W) * dinv ---------------
// Warp tile: 32 rows x 32 cols (2 m16 tiles x 4 n8 tiles), K=128 in 16 k8 steps.
// mma.m16n8k8.row.col: A row-major [M,128], B = W[k][c] (col n, row k).
// SRC: 0 = A param (x), 1 = g_h.
template <int SRC>
__global__ void __launch_bounds__(256) k_gemm_tc(
    const float* __restrict__ Ain, const float* __restrict__ W)
{
    const float* __restrict__ A = (SRC == 0) ? Ain : (const float*)g_h;

    const int lane = threadIdx.x & 31;
    const int warp = threadIdx.x >> 5;
    const int gw = blockIdx.x * 8 + warp;
    if (gw >= TC_WARPS) return;

    const int m0 = (gw >> 2) * 32;      // row stripe (100000 % 32 == 0, no guard)
    const int c0 = (gw & 3) * 32;       // col quarter
    const int qid = lane >> 2;          // 0..7
    const int t4 = lane & 3;            // 0..3

    float d[2][4][4];
#pragma unroll
    for (int mt = 0; mt < 2; mt++)
#pragma unroll
        for (int nt = 0; nt < 4; nt++)
#pragma unroll
            for (int i = 0; i < 4; i++) d[mt][nt][i] = 0.f;

#pragma unroll 4
    for (int it = 0; it < 16; it++) {
        const int k = it * 8;
        unsigned a[2][4];
#pragma unroll
        for (int mt = 0; mt < 2; mt++) {
            const float* Ap = A + (size_t)(m0 + mt * 16 + qid) * 128 + k + t4;
            a[mt][0] = to_tf32(__ldg(Ap));
            a[mt][1] = to_tf32(__ldg(Ap + 8 * 128));
            a[mt][2] = to_tf32(__ldg(Ap + 4));
            a[mt][3] = to_tf32(__ldg(Ap + 8 * 128 + 4));
        }
#pragma unroll
        for (int nt = 0; nt < 4; nt++) {
            const float* Wp = W + (size_t)(k + t4) * 128 + c0 + nt * 8 + qid;
            unsigned b0 = to_tf32(__ldg(Wp));
            unsigned b1 = to_tf32(__ldg(Wp + 4 * 128));
            mma_tf32(d[0][nt][0], d[0][nt][1], d[0][nt][2], d[0][nt][3],
                     a[0][0], a[0][1], a[0][2], a[0][3], b0, b1);
            mma_tf32(d[1][nt][0], d[1][nt][1], d[1][nt][2], d[1][nt][3],
                     a[1][0], a[1][1], a[1][2], a[1][3], b0, b1);
        }
    }

#pragma unroll
    for (int mt = 0; mt < 2; mt++) {
        const int row = m0 + mt * 16 + qid;
        const float s0 = g_dinv[row];
        const float s1 = g_dinv[row + 8];
#pragma unroll
        for (int nt = 0; nt < 4; nt++) {
            const int col = c0 + nt * 8 + t4 * 2;
            *(float2*)(g_y + (size_t)row * 128 + col) =
                make_float2(d[mt][nt][0] * s0, d[mt][nt][1] * s0);
            *(float2*)(g_y + (size_t)(row + 8) * 128 + col) =
                make_float2(d[mt][nt][2] * s1, d[mt][nt][3] * s1);
        }
    }
}

// ---------------- scalar GEMM for FC head (proven R4 path) ------------------
// A = g_h [N,128] ++ action [N,16]; h = relu(A@fc1 + b1); q = h.fc2 + b2.
__global__ void __launch_bounds__(256) k_fc(
    const float* __restrict__ A2, const float* __restrict__ W,
    const float* __restrict__ bias, const float* __restrict__ w2,
    const float* __restrict__ w2b, float* __restrict__ out)
{
    const int lane = threadIdx.x & 31;
    const int warp = threadIdx.x >> 5;
    const int row0 = (blockIdx.x * 8 + warp) * 8;
    const int c4 = lane * 4;

    const float* __restrict__ Abase = (const float*)g_h;

    int rc[8];
#pragma unroll
    for (int r = 0; r < 8; r++) {
        int row = row0 + r;
        rc[r] = (row < N_NODES) ? row : (N_NODES - 1);
    }

    float4 acc[8];
#pragma unroll
    for (int r = 0; r < 8; r++) acc[r] = make_float4(0.f, 0.f, 0.f, 0.f);

#pragma unroll 2
    for (int kc = 0; kc < 36; kc++) {
        const int k = kc * 4;
        float4 w0 = __ldg((const float4*)(W + (size_t)(k + 0) * 128 + c4));
        float4 w1 = __ldg((const float4*)(W + (size_t)(k + 1) * 128 + c4));
        float4 w2v = __ldg((const float4*)(W + (size_t)(k + 2) * 128 + c4));
        float4 w3 = __ldg((const float4*)(W + (size_t)(k + 3) * 128 + c4));
#pragma unroll
        for (int r = 0; r < 8; r++) {
            float4 av;
            if (k < 128)
                av = __ldg((const float4*)(Abase + (size_t)rc[r] * 128 + k));
            else
                av = __ldg((const float4*)(A2 + (size_t)rc[r] * 16 + (k - 128)));
            acc[r].x += av.x * w0.x + av.y * w1.x + av.z * w2v.x + av.w * w3.x;
            acc[r].y += av.x * w0.y + av.y * w1.y + av.z * w2v.y + av.w * w3.y;
            acc[r].z += av.x * w0.z + av.y * w1.z + av.z * w2v.z + av.w * w3.z;
            acc[r].w += av.x * w0.w + av.y * w1.w + av.z * w2v.w + av.w * w3.w;
        }
    }

    float4 b4 = __ldg((const float4*)(bias + c4));
    float4 wv = __ldg((const float4*)(w2 + c4));
    float ob = __ldg(w2b);
#pragma unroll
    for (int r = 0; r < 8; r++) {
        float hx = fmaxf(acc[r].x + b4.x, 0.f);
        float hy = fmaxf(acc[r].y + b4.y, 0.f);
        float hz = fmaxf(acc[r].z + b4.z, 0.f);
        float hw = fmaxf(acc[r].w + b4.w, 0.f);
        float p = hx * wv.x + hy * wv.y + hz * wv.z + hw * wv.w;
        p += __shfl_xor_sync(0xFFFFFFFFu, p, 16);
        p += __shfl_xor_sync(0xFFFFFFFFu, p, 8);
        p += __shfl_xor_sync(0xFFFFFFFFu, p, 4);
        p += __shfl_xor_sync(0xFFFFFFFFu, p, 2);
        p += __shfl_xor_sync(0xFFFFFFFFu, p, 1);
        int row = row0 + r;
        if (lane == 0 && row < N_NODES) out[row] = p + ob;
    }
}

// ---------------- gather-aggregate: one warp per dst row --------------------
// g_h[i][c] = relu( dinv[i] * ( g_y[i][c] + sum_{src in in(i)} g_y[src][c] ) + b[c] )
__global__ void __launch_bounds__(256) k_aggregate(
    const float* __restrict__ bias)
{
    const int lane = threadIdx.x & 31;
    const int warp = threadIdx.x >> 5;
    const int row = blockIdx.x * 8 + warp;
    if (row >= N_NODES) return;

    const int s = g_rowptr[row];
    const int e = g_rowptr[row + 1];
    const float4* yv = (const float4*)g_y;

    float4 a0 = __ldg(&yv[(size_t)row * 32 + lane]);  // self-loop term
    float4 a1 = make_float4(0.f, 0.f, 0.f, 0.f);
    float4 a2 = a1, a3 = a1;

    int i = s;
    for (; i + 4 <= e; i += 4) {
        int i0 = g_csr[i + 0];
        int i1 = g_csr[i + 1];
        int i2 = g_csr[i + 2];
        int i3 = g_csr[i + 3];
        a0 = f4add(a0, __ldg(&yv[(size_t)i0 * 32 + lane]));
        a1 = f4add(a1, __ldg(&yv[(size_t)i1 * 32 + lane]));
        a2 = f4add(a2, __ldg(&yv[(size_t)i2 * 32 + lane]));
        a3 = f4add(a3, __ldg(&yv[(size_t)i3 * 32 + lane]));
    }
    for (; i < e; i++) {
        int ix = g_csr[i];
        a0 = f4add(a0, __ldg(&yv[(size_t)ix * 32 + lane]));
    }
    float4 a = f4add(f4add(a0, a1), f4add(a2, a3));

    const float d = g_dinv[row];
    float4 b4 = __ldg((const float4*)(bias + lane * 4));
    float4 o = make_float4(fmaxf(a.x * d + b4.x, 0.f),
                           fmaxf(a.y * d + b4.y, 0.f),
                           fmaxf(a.z * d + b4.z, 0.f),
                           fmaxf(a.w * d + b4.w, 0.f));
    *(float4*)(g_h + (size_t)row * 128 + lane * 4) = o;
}

// ---------------- launch ----------------------------------------------------
extern "C" void kernel_launch(void* const* d_in, const int* in_sizes, int n_in,
                              void* d_out, int out_size)
{
    const float* x      = (const float*)d_in[0];
    const int*   ei     = (const int*)d_in[1];   // int32 (JAX x64 off); detect guards int64
    const float* action = (const float*)d_in[2];
    const float* g1w    = (const float*)d_in[3];
    const float* g1b    = (const float*)d_in[4];
    const float* g2w    = (const float*)d_in[5];
    const float* g2b    = (const float*)d_in[6];
    const float* f1w    = (const float*)d_in[7];
    const float* f1b    = (const float*)d_in[8];
    const float* f2w    = (const float*)d_in[9];
    const float* f2b    = (const float*)d_in[10];
    float*       q      = (float*)d_out;

    const int tc_grid   = (TC_WARPS + 7) / 8;        // 1563
    const int fc_grid   = (N_NODES + 63) / 64;
    const int agg_grid  = (N_NODES + 7) / 8;

    // CSR build + dinv
    k_detect<<<1, 32>>>(ei);
    k_init<<<(N_NODES + 1023) / 1024, 1024>>>();
    k_hist<<<(N_EDGES + 255) / 256, 256>>>(ei);
    k_scan1<<<SCAN_BLOCKS, 1024>>>();
    k_scan2<<<1, 32>>>();
    k_scan3<<<SCAN_BLOCKS, 1024>>>();
    k_fill<<<(N_EDGES + 255) / 256, 256>>>(ei);

    // Layer 1: g_y = (x @ W1) * dinv ; g_h = relu(dinv*(y_self + sum y[src]) + b1)
    k_gemm_tc<0><<<tc_grid, 256>>>(x, g1w);
    k_aggregate<<<agg_grid, 256>>>(g1b);

    // Layer 2
    k_gemm_tc<1><<<tc_grid, 256>>>(nullptr, g2w);
    k_aggregate<<<agg_grid, 256>>>(g2b);

    // FC head: relu([g_h|action] @ fc1 + b) . fc2 + b2  (fused)
    k_fc<<<fc_grid, 256>>>(action, f1w, f1b, f2w, f2b, q);
}

// round 7
// speedup vs baseline: 2.2793x; 1.3709x over previous
#include <cuda_runtime.h>
#include <cuda_fp16.h>

#define N_NODES 100000
#define N_EDGES 1600000
#define SCAN_BLOCKS 98   // ceil(100000/1024)
#define TC_WARPS 12500   // (100000/32 row stripes) * (128/32 col tiles)
#define FC_WARPS 6250    // 100000 / 16 rows per warp

// ---------------- scratch (static __device__ allocations; no cudaMalloc) ----
__device__ __half g_y16[(size_t)N_NODES * 128];  // (A@W)*dinv buffer (fp16)
__device__ float  g_h[(size_t)N_NODES * 128];    // post-aggregate hidden buffer
__device__ int    g_cnt[N_NODES];
__device__ int    g_rowptr[N_NODES + 1];
__device__ int    g_cursor[N_NODES];
__device__ float  g_dinv[N_NODES];
__device__ int    g_csr[N_EDGES];
__device__ int    g_bsums[SCAN_BLOCKS];
__device__ int    g_is64;

// ---------------- helpers ---------------------------------------------------
__device__ __forceinline__ unsigned to_tf32(float x) {
    unsigned r;
    asm("cvt.rna.tf32.f32 %0, %1;" : "=r"(r) : "f"(x));
    return r;
}

__device__ __forceinline__ void mma_tf32(
    float& d0, float& d1, float& d2, float& d3,
    unsigned a0, unsigned a1, unsigned a2, unsigned a3,
    unsigned b0, unsigned b1)
{
    asm("mma.sync.aligned.m16n8k8.row.col.f32.tf32.tf32.f32 "
        "{%0,%1,%2,%3}, {%4,%5,%6,%7}, {%8,%9}, {%0,%1,%2,%3};"
        : "+f"(d0), "+f"(d1), "+f"(d2), "+f"(d3)
        : "r"(a0), "r"(a1), "r"(a2), "r"(a3), "r"(b0), "r"(b1));
}

// Fetch (src, dst) of edge e, supporting int32 (expected) or int64 layout.
__device__ __forceinline__ void edge_fetch(const int* __restrict__ ei, int e,
                                           int& src, int& dst, int is64) {
    if (is64) {
        src = ei[2 * e];
        dst = ei[2 * (N_EDGES + e)];
    } else {
        src = ei[e];
        dst = ei[N_EDGES + e];
    }
}

// ---------------- dtype detection -------------------------------------------
__global__ void k_detect(const int* __restrict__ ei) {
    if (threadIdx.x == 0) {
        int acc = 0;
        for (int i = 0; i < 64; i++) acc |= ei[2 * i + 1];
        g_is64 = (acc == 0) ? 1 : 0;
    }
}

// ---------------- CSR construction ------------------------------------------
__global__ void k_init() {
    int i = blockIdx.x * blockDim.x + threadIdx.x;
    if (i < N_NODES) g_cnt[i] = 0;
}

__global__ void k_hist(const int* __restrict__ ei) {
    int e = blockIdx.x * blockDim.x + threadIdx.x;
    if (e < N_EDGES) {
        int src, dst;
        edge_fetch(ei, e, src, dst, g_is64);
        if ((unsigned)dst < N_NODES) atomicAdd(&g_cnt[dst], 1);
    }
}

__global__ void k_scan1() {
    __shared__ int sm[1024];
    int i = blockIdx.x * 1024 + threadIdx.x;
    int v = (i < N_NODES) ? g_cnt[i] : 0;
    sm[threadIdx.x] = v;
    __syncthreads();
#pragma unroll
    for (int off = 1; off < 1024; off <<= 1) {
        int t = (threadIdx.x >= off) ? sm[threadIdx.x - off] : 0;
        __syncthreads();
        sm[threadIdx.x] += t;
        __syncthreads();
    }
    int incl = sm[threadIdx.x];
    if (i < N_NODES) g_rowptr[i] = incl - v;     // block-local exclusive
    if (threadIdx.x == 1023) g_bsums[blockIdx.x] = incl;
}

__global__ void k_scan2() {
    if (threadIdx.x == 0) {
        int run = 0;
        for (int b = 0; b < SCAN_BLOCKS; b++) {
            int v = g_bsums[b];
            g_bsums[b] = run;
            run += v;
        }
    }
}

__global__ void k_scan3() {
    int i = blockIdx.x * 1024 + threadIdx.x;
    if (i < N_NODES) {
        int rp = g_rowptr[i] + g_bsums[blockIdx.x];
        g_rowptr[i] = rp;
        g_cursor[i] = rp;
        g_dinv[i] = rsqrtf((float)(g_cnt[i] + 1));  // +1 self-loop
    }
    if (i == 0) g_rowptr[N_NODES] = N_EDGES;
}

__global__ void k_fill(const int* __restrict__ ei) {
    int e = blockIdx.x * blockDim.x + threadIdx.x;
    if (e < N_EDGES) {
        int src, dst;
        edge_fetch(ei, e, src, dst, g_is64);
        if ((unsigned)dst < N_NODES && (unsigned)src < N_NODES) {
            int pos = atomicAdd(&g_cursor[dst], 1);
            g_csr[pos] = src;
        }
    }
}

// ---------------- tf32 tensor-core GEMM: g_y16 = half((A @ W) * dinv) -------
// Warp tile: 32 rows x 32 cols (2 m16 tiles x 4 n8 tiles), K=128 in 16 k8 steps.
// SRC: 0 = A param (x), 1 = g_h.
template <int SRC>
__global__ void __launch_bounds__(256) k_gemm_tc(
    const float* __restrict__ Ain, const float* __restrict__ W)
{
    const float* __restrict__ A = (SRC == 0) ? Ain : (const float*)g_h;

    const int lane = threadIdx.x & 31;
    const int warp = threadIdx.x >> 5;
    const int gw = blockIdx.x * 8 + warp;
    if (gw >= TC_WARPS) return;

    const int m0 = (gw >> 2) * 32;      // row stripe (100000 % 32 == 0, no guard)
    const int c0 = (gw & 3) * 32;       // col quarter
    const int qid = lane >> 2;          // 0..7
    const int t4 = lane & 3;            // 0..3

    float d[2][4][4];
#pragma unroll
    for (int mt = 0; mt < 2; mt++)
#pragma unroll
        for (int nt = 0; nt < 4; nt++)
#pragma unroll
            for (int i = 0; i < 4; i++) d[mt][nt][i] = 0.f;

#pragma unroll 4
    for (int it = 0; it < 16; it++) {
        const int k = it * 8;
        unsigned a[2][4];
#pragma unroll
        for (int mt = 0; mt < 2; mt++) {
            const float* Ap = A + (size_t)(m0 + mt * 16 + qid) * 128 + k + t4;
            a[mt][0] = to_tf32(__ldg(Ap));
            a[mt][1] = to_tf32(__ldg(Ap + 8 * 128));
            a[mt][2] = to_tf32(__ldg(Ap + 4));
            a[mt][3] = to_tf32(__ldg(Ap + 8 * 128 + 4));
        }
#pragma unroll
        for (int nt = 0; nt < 4; nt++) {
            const float* Wp = W + (size_t)(k + t4) * 128 + c0 + nt * 8 + qid;
            unsigned b0 = to_tf32(__ldg(Wp));
            unsigned b1 = to_tf32(__ldg(Wp + 4 * 128));
            mma_tf32(d[0][nt][0], d[0][nt][1], d[0][nt][2], d[0][nt][3],
                     a[0][0], a[0][1], a[0][2], a[0][3], b0, b1);
            mma_tf32(d[1][nt][0], d[1][nt][1], d[1][nt][2], d[1][nt][3],
                     a[1][0], a[1][1], a[1][2], a[1][3], b0, b1);
        }
    }

#pragma unroll
    for (int mt = 0; mt < 2; mt++) {
        const int row = m0 + mt * 16 + qid;
        const float s0 = g_dinv[row];
        const float s1 = g_dinv[row + 8];
#pragma unroll
        for (int nt = 0; nt < 4; nt++) {
            const int col = c0 + nt * 8 + t4 * 2;
            *(__half2*)(g_y16 + (size_t)row * 128 + col) =
                __floats2half2_rn(d[mt][nt][0] * s0, d[mt][nt][1] * s0);
            *(__half2*)(g_y16 + (size_t)(row + 8) * 128 + col) =
                __floats2half2_rn(d[mt][nt][2] * s1, d[mt][nt][3] * s1);
        }
    }
}

// ---------------- tf32 FC head: q = relu([g_h|action]@fc1 + b1) . fc2 + b2 --
// Warp = 16 rows x 128 cols (16 n8 tiles), K=144 in 18 k8 steps; fc2 fused.
__global__ void __launch_bounds__(256) k_fc_tc(
    const float* __restrict__ act, const float* __restrict__ W,
    const float* __restrict__ bias, const float* __restrict__ w2,
    const float* __restrict__ w2b, float* __restrict__ out)
{
    const int lane = threadIdx.x & 31;
    const int warp = threadIdx.x >> 5;
    const int gw = blockIdx.x * 8 + warp;
    if (gw >= FC_WARPS) return;

    const int m0 = gw * 16;             // 100000 = 6250*16, no guard
    const int qid = lane >> 2;
    const int t4 = lane & 3;

    float d[16][4];
#pragma unroll
    for (int nt = 0; nt < 16; nt++)
#pragma unroll
        for (int i = 0; i < 4; i++) d[nt][i] = 0.f;

#pragma unroll 2
    for (int kt = 0; kt < 18; kt++) {
        const int k = kt * 8;
        unsigned a0, a1, a2, a3;
        if (k < 128) {
            const float* Ap = (const float*)g_h + (size_t)(m0 + qid) * 128 + k + t4;
            a0 = to_tf32(__ldg(Ap));
            a1 = to_tf32(__ldg(Ap + 8 * 128));
            a2 = to_tf32(__ldg(Ap + 4));
            a3 = to_tf32(__ldg(Ap + 8 * 128 + 4));
        } else {
            const float* Ap = act + (size_t)(m0 + qid) * 16 + (k - 128) + t4;
            a0 = to_tf32(__ldg(Ap));
            a1 = to_tf32(__ldg(Ap + 8 * 16));
            a2 = to_tf32(__ldg(Ap + 4));
            a3 = to_tf32(__ldg(Ap + 8 * 16 + 4));
        }
#pragma unroll
        for (int nt = 0; nt < 16; nt++) {
            const float* Wp = W + (size_t)(k + t4) * 128 + nt * 8 + qid;
            unsigned b0 = to_tf32(__ldg(Wp));
            unsigned b1 = to_tf32(__ldg(Wp + 4 * 128));
            mma_tf32(d[nt][0], d[nt][1], d[nt][2], d[nt][3],
                     a0, a1, a2, a3, b0, b1);
        }
    }

    // epilogue: relu(+bias) then dot with fc2 weights, quad-reduce
    float plo = 0.f, phi = 0.f;
#pragma unroll
    for (int nt = 0; nt < 16; nt++) {
        const int col = nt * 8 + t4 * 2;
        float2 b2 = *(const float2*)(bias + col);
        float2 wv = *(const float2*)(w2 + col);
        plo += fmaxf(d[nt][0] + b2.x, 0.f) * wv.x + fmaxf(d[nt][1] + b2.y, 0.f) * wv.y;
        phi += fmaxf(d[nt][2] + b2.x, 0.f) * wv.x + fmaxf(d[nt][3] + b2.y, 0.f) * wv.y;
    }
    plo += __shfl_xor_sync(0xFFFFFFFFu, plo, 1);
    plo += __shfl_xor_sync(0xFFFFFFFFu, plo, 2);
    phi += __shfl_xor_sync(0xFFFFFFFFu, phi, 1);
    phi += __shfl_xor_sync(0xFFFFFFFFu, phi, 2);
    if (t4 == 0) {
        float ob = __ldg(w2b);
        out[m0 + qid] = plo + ob;
        out[m0 + qid + 8] = phi + ob;
    }
}

// ---------------- gather-aggregate: one warp per dst row (fp16 y) -----------
// g_h[i][c] = relu( dinv[i] * ( y[i][c] + sum_{src in in(i)} y[src][c] ) + b[c] )
__global__ void __launch_bounds__(256) k_aggregate(
    const float* __restrict__ bias)
{
    const int lane = threadIdx.x & 31;
    const int warp = threadIdx.x >> 5;
    const int row = blockIdx.x * 8 + warp;
    if (row >= N_NODES) return;

    const int s = g_rowptr[row];
    const int e = g_rowptr[row + 1];
    const uint2* yv = (const uint2*)g_y16;   // 4 halfs (8 B) per lane; row stride 32

    float4 a0, a1, a2, a3;
    {
        uint2 u = __ldg(&yv[(size_t)row * 32 + lane]);  // self-loop term
        float2 f0 = __half22float2(*(__half2*)&u.x);
        float2 f1 = __half22float2(*(__half2*)&u.y);
        a0 = make_float4(f0.x, f0.y, f1.x, f1.y);
    }
    a1 = make_float4(0.f, 0.f, 0.f, 0.f);
    a2 = a1; a3 = a1;

    int i = s;
    for (; i + 4 <= e; i += 4) {
        int i0 = g_csr[i + 0];
        int i1 = g_csr[i + 1];
        int i2 = g_csr[i + 2];
        int i3 = g_csr[i + 3];
        uint2 u0 = __ldg(&yv[(size_t)i0 * 32 + lane]);
        uint2 u1 = __ldg(&yv[(size_t)i1 * 32 + lane]);
        uint2 u2 = __ldg(&yv[(size_t)i2 * 32 + lane]);
        uint2 u3 = __ldg(&yv[(size_t)i3 * 32 + lane]);
        float2 f;
        f = __half22float2(*(__half2*)&u0.x); a0.x += f.x; a0.y += f.y;
        f = __half22float2(*(__half2*)&u0.y); a0.z += f.x; a0.w += f.y;
        f = __half22float2(*(__half2*)&u1.x); a1.x += f.x; a1.y += f.y;
        f = __half22float2(*(__half2*)&u1.y); a1.z += f.x; a1.w += f.y;
        f = __half22float2(*(__half2*)&u2.x); a2.x += f.x; a2.y += f.y;
        f = __half22float2(*(__half2*)&u2.y); a2.z += f.x; a2.w += f.y;
        f = __half22float2(*(__half2*)&u3.x); a3.x += f.x; a3.y += f.y;
        f = __half22float2(*(__half2*)&u3.y); a3.z += f.x; a3.w += f.y;
    }
    for (; i < e; i++) {
        int ix = g_csr[i];
        uint2 u = __ldg(&yv[(size_t)ix * 32 + lane]);
        float2 f;
        f = __half22float2(*(__half2*)&u.x); a0.x += f.x; a0.y += f.y;
        f = __half22float2(*(__half2*)&u.y); a0.z += f.x; a0.w += f.y;
    }
    float4 a = make_float4(a0.x + a1.x + a2.x + a3.x,
                           a0.y + a1.y + a2.y + a3.y,
                           a0.z + a1.z + a2.z + a3.z,
                           a0.w + a1.w + a2.w + a3.w);

    const float dv = g_dinv[row];
    float4 b4 = __ldg((const float4*)(bias + lane * 4));
    float4 o = make_float4(fmaxf(a.x * dv + b4.x, 0.f),
                           fmaxf(a.y * dv + b4.y, 0.f),
                           fmaxf(a.z * dv + b4.z, 0.f),
                           fmaxf(a.w * dv + b4.w, 0.f));
    *(float4*)(g_h + (size_t)row * 128 + lane * 4) = o;
}

// ---------------- launch ----------------------------------------------------
extern "C" void kernel_launch(void* const* d_in, const int* in_sizes, int n_in,
                              void* d_out, int out_size)
{
    const float* x      = (const float*)d_in[0];
    const int*   ei     = (const int*)d_in[1];   // int32 (JAX x64 off); detect guards int64
    const float* action = (const float*)d_in[2];
    const float* g1w    = (const float*)d_in[3];
    const float* g1b    = (const float*)d_in[4];
    const float* g2w    = (const float*)d_in[5];
    const float* g2b    = (const float*)d_in[6];
    const float* f1w    = (const float*)d_in[7];
    const float* f1b    = (const float*)d_in[8];
    const float* f2w    = (const float*)d_in[9];
    const float* f2b    = (const float*)d_in[10];
    float*       q      = (float*)d_out;

    const int tc_grid  = (TC_WARPS + 7) / 8;        // 1563
    const int fc_grid  = (FC_WARPS + 7) / 8;        // 782
    const int agg_grid = (N_NODES + 7) / 8;

    // CSR build + dinv
    k_detect<<<1, 32>>>(ei);
    k_init<<<(N_NODES + 1023) / 1024, 1024>>>();
    k_hist<<<(N_EDGES + 255) / 256, 256>>>(ei);
    k_scan1<<<SCAN_BLOCKS, 1024>>>();
    k_scan2<<<1, 32>>>();
    k_scan3<<<SCAN_BLOCKS, 1024>>>();
    k_fill<<<(N_EDGES + 255) / 256, 256>>>(ei);

    // Layer 1: y = half((x@W1)*dinv) ; g_h = relu(dinv*(y_self + sum y[src]) + b1)
    k_gemm_tc<0><<<tc_grid, 256>>>(x, g1w);
    k_aggregate<<<agg_grid, 256>>>(g1b);

    // Layer 2
    k_gemm_tc<1><<<tc_grid, 256>>>(nullptr, g2w);
    k_aggregate<<<agg_grid, 256>>>(g2b);

    // FC head (tensor-core, fc2 fused)
    k_fc_tc<<<fc_grid, 256>>>(action, f1w, f1b, f2w, f2b, q);
}

// round 8
// speedup vs baseline: 2.4967x; 1.0954x over previous
#include <cuda_runtime.h>
#include <cuda_fp16.h>

#define N_NODES 100000
#define N_EDGES 1600000
#define SCAN_BLOCKS 98   // ceil(100000/1024)
#define TC_WARPS 6250    // (100000/32 row stripes) * (128/64 col halves)
#define FC_WARPS 6250    // 100000 / 16 rows per warp

typedef unsigned long long ull;

// ---------------- scratch (static __device__ allocations; no cudaMalloc) ----
__device__ __half g_y16[(size_t)N_NODES * 128];  // (A@W)*dinv buffer (fp16)
__device__ float  g_h[(size_t)N_NODES * 128];    // post-aggregate hidden buffer
__device__ int    g_cnt[N_NODES];
__device__ int    g_rowptr[N_NODES + 1];
__device__ int    g_cursor[N_NODES];
__device__ float  g_dinv[N_NODES];
__device__ int    g_csr[N_EDGES];
__device__ ull    g_scan_pkt[SCAN_BLOCKS];       // (flag<<32) | value
__device__ int    g_is64;

// ---------------- helpers ---------------------------------------------------
__device__ __forceinline__ unsigned to_tf32(float x) {
    unsigned r;
    asm("cvt.rna.tf32.f32 %0, %1;" : "=r"(r) : "f"(x));
    return r;
}

__device__ __forceinline__ void mma_tf32(
    float& d0, float& d1, float& d2, float& d3,
    unsigned a0, unsigned a1, unsigned a2, unsigned a3,
    unsigned b0, unsigned b1)
{
    asm("mma.sync.aligned.m16n8k8.row.col.f32.tf32.tf32.f32 "
        "{%0,%1,%2,%3}, {%4,%5,%6,%7}, {%8,%9}, {%0,%1,%2,%3};"
        : "+f"(d0), "+f"(d1), "+f"(d2), "+f"(d3)
        : "r"(a0), "r"(a1), "r"(a2), "r"(a3), "r"(b0), "r"(b1));
}

__device__ __forceinline__ void edge_fetch(const int* __restrict__ ei, int e,
                                           int& src, int& dst, int is64) {
    if (is64) {
        src = ei[2 * e];
        dst = ei[2 * (N_EDGES + e)];
    } else {
        src = ei[e];
        dst = ei[N_EDGES + e];
    }
}

// ---------------- init + dtype detection (fused) -----------------------------
// Zeroes g_cnt, resets scan packets, detects int32 vs int64 edge layout.
__global__ void k_detect_init(const int* __restrict__ ei) {
    int i = blockIdx.x * blockDim.x + threadIdx.x;
    if (i < N_NODES) g_cnt[i] = 0;
    if (i < SCAN_BLOCKS) g_scan_pkt[i] = 0ull;
    if (i == 0) {
        int acc = 0;
        for (int j = 0; j < 64; j++) acc |= ei[2 * j + 1];
        g_is64 = (acc == 0) ? 1 : 0;
    }
}

// ---------------- histogram --------------------------------------------------
__global__ void k_hist(const int* __restrict__ ei) {
    int e = blockIdx.x * blockDim.x + threadIdx.x;
    if (e < N_EDGES) {
        int src, dst;
        edge_fetch(ei, e, src, dst, g_is64);
        if ((unsigned)dst < N_NODES) atomicAdd(&g_cnt[dst], 1);
    }
}

// ---------------- single-pass scan (decoupled lookback) + rowptr/dinv --------
__global__ void __launch_bounds__(1024) k_scan() {
    __shared__ int sm[1024];
    __shared__ int s_prefix;
    const int b = blockIdx.x;
    const int i = b * 1024 + threadIdx.x;
    const int v = (i < N_NODES) ? g_cnt[i] : 0;
    sm[threadIdx.x] = v;
    __syncthreads();
#pragma unroll
    for (int off = 1; off < 1024; off <<= 1) {
        int t = (threadIdx.x >= off) ? sm[threadIdx.x - off] : 0;
        __syncthreads();
        sm[threadIdx.x] += t;
        __syncthreads();
    }
    const int incl = sm[threadIdx.x];

    if (threadIdx.x == 0) {
        const int total = sm[1023];
        if (b == 0) {
            atomicExch(&g_scan_pkt[0], (2ull << 32) | (unsigned)total);
            s_prefix = 0;
        } else {
            atomicExch(&g_scan_pkt[b], (1ull << 32) | (unsigned)total);
            int pfx = 0;
            int j = b - 1;
            while (true) {
                ull w;
                do { w = *(volatile ull*)&g_scan_pkt[j]; } while ((w >> 32) == 0);
                pfx += (int)(unsigned)w;
                if ((w >> 32) == 2ull) break;
                j--;
            }
            atomicExch(&g_scan_pkt[b], (2ull << 32) | (unsigned)(pfx + total));
            s_prefix = pfx;
        }
    }
    __syncthreads();
    const int pfx = s_prefix;
    if (i < N_NODES) {
        const int rp = pfx + incl - v;
        g_rowptr[i] = rp;
        g_cursor[i] = rp;
        g_dinv[i] = rsqrtf((float)(g_cnt[i] + 1));  // +1 self-loop
    }
    if (i == 0) g_rowptr[N_NODES] = N_EDGES;
}

__global__ void k_fill(const int* __restrict__ ei) {
    int e = blockIdx.x * blockDim.x + threadIdx.x;
    if (e < N_EDGES) {
        int src, dst;
        edge_fetch(ei, e, src, dst, g_is64);
        if ((unsigned)dst < N_NODES && (unsigned)src < N_NODES) {
            int pos = atomicAdd(&g_cursor[dst], 1);
            g_csr[pos] = src;
        }
    }
}

// ---------------- tf32 tensor-core GEMM: g_y16 = half((A @ W) * dinv) -------
// Warp tile: 32 rows x 64 cols (2 m16 tiles x 8 n8 tiles), K=128 in 16 k8 steps.
// SRC: 0 = A param (x), 1 = g_h.
template <int SRC>
__global__ void __launch_bounds__(256) k_gemm_tc(
    const float* __restrict__ Ain, const float* __restrict__ W)
{
    const float* __restrict__ A = (SRC == 0) ? Ain : (const float*)g_h;

    const int lane = threadIdx.x & 31;
    const int warp = threadIdx.x >> 5;
    const int gw = blockIdx.x * 8 + warp;
    if (gw >= TC_WARPS) return;

    const int m0 = (gw >> 1) * 32;      // row stripe (100000 % 32 == 0)
    const int c0 = (gw & 1) * 64;       // col half
    const int qid = lane >> 2;          // 0..7
    const int t4 = lane & 3;            // 0..3

    float d[2][8][4];
#pragma unroll
    for (int mt = 0; mt < 2; mt++)
#pragma unroll
        for (int nt = 0; nt < 8; nt++)
#pragma unroll
            for (int i = 0; i < 4; i++) d[mt][nt][i] = 0.f;

#pragma unroll 2
    for (int it = 0; it < 16; it++) {
        const int k = it * 8;
        unsigned a[2][4];
#pragma unroll
        for (int mt = 0; mt < 2; mt++) {
            const float* Ap = A + (size_t)(m0 + mt * 16 + qid) * 128 + k + t4;
            a[mt][0] = to_tf32(__ldg(Ap));
            a[mt][1] = to_tf32(__ldg(Ap + 8 * 128));
            a[mt][2] = to_tf32(__ldg(Ap + 4));
            a[mt][3] = to_tf32(__ldg(Ap + 8 * 128 + 4));
        }
#pragma unroll
        for (int nt = 0; nt < 8; nt++) {
            const float* Wp = W + (size_t)(k + t4) * 128 + c0 + nt * 8 + qid;
            unsigned b0 = to_tf32(__ldg(Wp));
            unsigned b1 = to_tf32(__ldg(Wp + 4 * 128));
            mma_tf32(d[0][nt][0], d[0][nt][1], d[0][nt][2], d[0][nt][3],
                     a[0][0], a[0][1], a[0][2], a[0][3], b0, b1);
            mma_tf32(d[1][nt][0], d[1][nt][1], d[1][nt][2], d[1][nt][3],
                     a[1][0], a[1][1], a[1][2], a[1][3], b0, b1);
        }
    }

#pragma unroll
    for (int mt = 0; mt < 2; mt++) {
        const int row = m0 + mt * 16 + qid;
        const float s0 = g_dinv[row];
        const float s1 = g_dinv[row + 8];
#pragma unroll
        for (int nt = 0; nt < 8; nt++) {
            const int col = c0 + nt * 8 + t4 * 2;
            *(__half2*)(g_y16 + (size_t)row * 128 + col) =
                __floats2half2_rn(d[mt][nt][0] * s0, d[mt][nt][1] * s0);
            *(__half2*)(g_y16 + (size_t)(row + 8) * 128 + col) =
                __floats2half2_rn(d[mt][nt][2] * s1, d[mt][nt][3] * s1);
        }
    }
}

// ---------------- tf32 FC head: q = relu([g_h|action]@fc1 + b1) . fc2 + b2 --
__global__ void __launch_bounds__(256) k_fc_tc(
    const float* __restrict__ act, const float* __restrict__ W,
    const float* __restrict__ bias, const float* __restrict__ w2,
    const float* __restrict__ w2b, float* __restrict__ out)
{
    const int lane = threadIdx.x & 31;
    const int warp = threadIdx.x >> 5;
    const int gw = blockIdx.x * 8 + warp;
    if (gw >= FC_WARPS) return;

    const int m0 = gw * 16;             // 100000 = 6250*16
    const int qid = lane >> 2;
    const int t4 = lane & 3;

    float d[16][4];
#pragma unroll
    for (int nt = 0; nt < 16; nt++)
#pragma unroll
        for (int i = 0; i < 4; i++) d[nt][i] = 0.f;

#pragma unroll 2
    for (int kt = 0; kt < 18; kt++) {
        const int k = kt * 8;
        unsigned a0, a1, a2, a3;
        if (k < 128) {
            const float* Ap = (const float*)g_h + (size_t)(m0 + qid) * 128 + k + t4;
            a0 = to_tf32(__ldg(Ap));
            a1 = to_tf32(__ldg(Ap + 8 * 128));
            a2 = to_tf32(__ldg(Ap + 4));
            a3 = to_tf32(__ldg(Ap + 8 * 128 + 4));
        } else {
            const float* Ap = act + (size_t)(m0 + qid) * 16 + (k - 128) + t4;
            a0 = to_tf32(__ldg(Ap));
            a1 = to_tf32(__ldg(Ap + 8 * 16));
            a2 = to_tf32(__ldg(Ap + 4));
            a3 = to_tf32(__ldg(Ap + 8 * 16 + 4));
        }
#pragma unroll
        for (int nt = 0; nt < 16; nt++) {
            const float* Wp = W + (size_t)(k + t4) * 128 + nt * 8 + qid;
            unsigned b0 = to_tf32(__ldg(Wp));
            unsigned b1 = to_tf32(__ldg(Wp + 4 * 128));
            mma_tf32(d[nt][0], d[nt][1], d[nt][2], d[nt][3],
                     a0, a1, a2, a3, b0, b1);
        }
    }

    float plo = 0.f, phi = 0.f;
#pragma unroll
    for (int nt = 0; nt < 16; nt++) {
        const int col = nt * 8 + t4 * 2;
        float2 b2 = *(const float2*)(bias + col);
        float2 wv = *(const float2*)(w2 + col);
        plo += fmaxf(d[nt][0] + b2.x, 0.f) * wv.x + fmaxf(d[nt][1] + b2.y, 0.f) * wv.y;
        phi += fmaxf(d[nt][2] + b2.x, 0.f) * wv.x + fmaxf(d[nt][3] + b2.y, 0.f) * wv.y;
    }
    plo += __shfl_xor_sync(0xFFFFFFFFu, plo, 1);
    plo += __shfl_xor_sync(0xFFFFFFFFu, plo, 2);
    phi += __shfl_xor_sync(0xFFFFFFFFu, phi, 1);
    phi += __shfl_xor_sync(0xFFFFFFFFu, phi, 2);
    if (t4 == 0) {
        float ob = __ldg(w2b);
        out[m0 + qid] = plo + ob;
        out[m0 + qid + 8] = phi + ob;
    }
}

// ---------------- gather-aggregate: one warp per dst row (fp16 y) -----------
__global__ void __launch_bounds__(256) k_aggregate(
    const float* __restrict__ bias)
{
    const int lane = threadIdx.x & 31;
    const int warp = threadIdx.x >> 5;
    const int row = blockIdx.x * 8 + warp;
    if (row >= N_NODES) return;

    const int s = g_rowptr[row];
    const int e = g_rowptr[row + 1];
    const uint2* yv = (const uint2*)g_y16;   // 4 halfs (8 B) per lane; row stride 32

    float4 a0, a1, a2, a3;
    {
        uint2 u = __ldg(&yv[(size_t)row * 32 + lane]);  // self-loop term
        float2 f0 = __half22float2(*(__half2*)&u.x);
        float2 f1 = __half22float2(*(__half2*)&u.y);
        a0 = make_float4(f0.x, f0.y, f1.x, f1.y);
    }
    a1 = make_float4(0.f, 0.f, 0.f, 0.f);
    a2 = a1; a3 = a1;

    int i = s;
    for (; i + 4 <= e; i += 4) {
        int i0 = g_csr[i + 0];
        int i1 = g_csr[i + 1];
        int i2 = g_csr[i + 2];
        int i3 = g_csr[i + 3];
        uint2 u0 = __ldg(&yv[(size_t)i0 * 32 + lane]);
        uint2 u1 = __ldg(&yv[(size_t)i1 * 32 + lane]);
        uint2 u2 = __ldg(&yv[(size_t)i2 * 32 + lane]);
        uint2 u3 = __ldg(&yv[(size_t)i3 * 32 + lane]);
        float2 f;
        f = __half22float2(*(__half2*)&u0.x); a0.x += f.x; a0.y += f.y;
        f = __half22float2(*(__half2*)&u0.y); a0.z += f.x; a0.w += f.y;
        f = __half22float2(*(__half2*)&u1.x); a1.x += f.x; a1.y += f.y;
        f = __half22float2(*(__half2*)&u1.y); a1.z += f.x; a1.w += f.y;
        f = __half22float2(*(__half2*)&u2.x); a2.x += f.x; a2.y += f.y;
        f = __half22float2(*(__half2*)&u2.y); a2.z += f.x; a2.w += f.y;
        f = __half22float2(*(__half2*)&u3.x); a3.x += f.x; a3.y += f.y;
        f = __half22float2(*(__half2*)&u3.y); a3.z += f.x; a3.w += f.y;
    }
    for (; i < e; i++) {
        int ix = g_csr[i];
        uint2 u = __ldg(&yv[(size_t)ix * 32 + lane]);
        float2 f;
        f = __half22float2(*(__half2*)&u.x); a0.x += f.x; a0.y += f.y;
        f = __half22float2(*(__half2*)&u.y); a0.z += f.x; a0.w += f.y;
    }
    float4 a = make_float4(a0.x + a1.x + a2.x + a3.x,
                           a0.y + a1.y + a2.y + a3.y,
                           a0.z + a1.z + a2.z + a3.z,
                           a0.w + a1.w + a2.w + a3.w);

    const float dv = g_dinv[row];
    float4 b4 = __ldg((const float4*)(bias + lane * 4));
    float4 o = make_float4(fmaxf(a.x * dv + b4.x, 0.f),
                           fmaxf(a.y * dv + b4.y, 0.f),
                           fmaxf(a.z * dv + b4.z, 0.f),
                           fmaxf(a.w * dv + b4.w, 0.f));
    *(float4*)(g_h + (size_t)row * 128 + lane * 4) = o;
}

// ---------------- launch ----------------------------------------------------
extern "C" void kernel_launch(void* const* d_in, const int* in_sizes, int n_in,
                              void* d_out, int out_size)
{
    const float* x      = (const float*)d_in[0];
    const int*   ei     = (const int*)d_in[1];   // int32 (JAX x64 off); detect guards int64
    const float* action = (const float*)d_in[2];
    const float* g1w    = (const float*)d_in[3];
    const float* g1b    = (const float*)d_in[4];
    const float* g2w    = (const float*)d_in[5];
    const float* g2b    = (const float*)d_in[6];
    const float* f1w    = (const float*)d_in[7];
    const float* f1b    = (const float*)d_in[8];
    const float* f2w    = (const float*)d_in[9];
    const float* f2b    = (const float*)d_in[10];
    float*       q      = (float*)d_out;

    const int tc_grid  = (TC_WARPS + 7) / 8;        // 782
    const int fc_grid  = (FC_WARPS + 7) / 8;        // 782
    const int agg_grid = (N_NODES + 7) / 8;

    // CSR build (launch order puts gemm1 at slot 3 for the ncu window)
    k_detect_init<<<SCAN_BLOCKS, 1024>>>(ei);                 // 0
    k_hist<<<(N_EDGES + 255) / 256, 256>>>(ei);               // 1
    k_scan<<<SCAN_BLOCKS, 1024>>>();                          // 2
    k_gemm_tc<0><<<tc_grid, 256>>>(x, g1w);                   // 3  <- profiled
    k_fill<<<(N_EDGES + 255) / 256, 256>>>(ei);               // 4

    // Layer 1 aggregate
    k_aggregate<<<agg_grid, 256>>>(g1b);                      // 5

    // Layer 2
    k_gemm_tc<1><<<tc_grid, 256>>>(nullptr, g2w);             // 6
    k_aggregate<<<agg_grid, 256>>>(g2b);                      // 7

    // FC head (tensor-core, fc2 fused)
    k_fc_tc<<<fc_grid, 256>>>(action, f1w, f1b, f2w, f2b, q); // 8
}

// round 9
// speedup vs baseline: 3.1491x; 1.2613x over previous
#include <cuda_runtime.h>
#include <cuda_fp16.h>

#define N_NODES 100000
#define N_EDGES 1600000
#define SCAN_BLOCKS 98   // ceil(100000/1024)
#define GEMM_BLOCKS 782  // ceil(100000/128)

// smem layouts (uint32 tf32 words)
#define SA_STRIDE 132        // 128 + 4 pad  -> frag bank (4*qid + t4) conflict-free
#define SW_STRIDE 136        // 128 + 8 pad  -> frag bank (8*t4 + qid) conflict-free
#define SAFC_STRIDE 148      // 144 + 4 pad  -> (20*qid + t4) mod 32 distinct
#define GEMM_SMEM ((128 * SA_STRIDE + 128 * SW_STRIDE) * 4)        // 137216 B
#define FC_SMEM   ((128 * SAFC_STRIDE + 144 * SW_STRIDE) * 4)      // 154112 B

typedef unsigned long long ull;

// ---------------- scratch (static __device__ allocations; no cudaMalloc) ----
__device__ __half g_y16[(size_t)N_NODES * 128];  // (A@W)*dinv buffer (fp16)
__device__ float  g_h[(size_t)N_NODES * 128];    // post-aggregate hidden buffer
__device__ int    g_cnt[N_NODES];
__device__ int    g_rowptr[N_NODES + 1];
__device__ int    g_cursor[N_NODES];
__device__ float  g_dinv[N_NODES];
__device__ int    g_csr[N_EDGES];
__device__ ull    g_scan_pkt[SCAN_BLOCKS];       // (flag<<32) | value
__device__ int    g_is64;

// ---------------- helpers ---------------------------------------------------
__device__ __forceinline__ unsigned to_tf32(float x) {
    unsigned r;
    asm("cvt.rna.tf32.f32 %0, %1;" : "=r"(r) : "f"(x));
    return r;
}

__device__ __forceinline__ void mma_tf32(
    float& d0, float& d1, float& d2, float& d3,
    unsigned a0, unsigned a1, unsigned a2, unsigned a3,
    unsigned b0, unsigned b1)
{
    asm("mma.sync.aligned.m16n8k8.row.col.f32.tf32.tf32.f32 "
        "{%0,%1,%2,%3}, {%4,%5,%6,%7}, {%8,%9}, {%0,%1,%2,%3};"
        : "+f"(d0), "+f"(d1), "+f"(d2), "+f"(d3)
        : "r"(a0), "r"(a1), "r"(a2), "r"(a3), "r"(b0), "r"(b1));
}

__device__ __forceinline__ void edge_fetch(const int* __restrict__ ei, int e,
                                           int& src, int& dst, int is64) {
    if (is64) {
        src = ei[2 * e];
        dst = ei[2 * (N_EDGES + e)];
    } else {
        src = ei[e];
        dst = ei[N_EDGES + e];
    }
}

// ---------------- init + dtype detection (fused) -----------------------------
__global__ void k_detect_init(const int* __restrict__ ei) {
    int i = blockIdx.x * blockDim.x + threadIdx.x;
    if (i < N_NODES) g_cnt[i] = 0;
    if (i < SCAN_BLOCKS) g_scan_pkt[i] = 0ull;
    if (i == 0) {
        int acc = 0;
        for (int j = 0; j < 64; j++) acc |= ei[2 * j + 1];
        g_is64 = (acc == 0) ? 1 : 0;
    }
}

__global__ void k_hist(const int* __restrict__ ei) {
    int e = blockIdx.x * blockDim.x + threadIdx.x;
    if (e < N_EDGES) {
        int src, dst;
        edge_fetch(ei, e, src, dst, g_is64);
        if ((unsigned)dst < N_NODES) atomicAdd(&g_cnt[dst], 1);
    }
}

// ---------------- single-pass scan (decoupled lookback) + rowptr/dinv --------
__global__ void __launch_bounds__(1024) k_scan() {
    __shared__ int sm[1024];
    __shared__ int s_prefix;
    const int b = blockIdx.x;
    const int i = b * 1024 + threadIdx.x;
    const int v = (i < N_NODES) ? g_cnt[i] : 0;
    sm[threadIdx.x] = v;
    __syncthreads();
#pragma unroll
    for (int off = 1; off < 1024; off <<= 1) {
        int t = (threadIdx.x >= off) ? sm[threadIdx.x - off] : 0;
        __syncthreads();
        sm[threadIdx.x] += t;
        __syncthreads();
    }
    const int incl = sm[threadIdx.x];

    if (threadIdx.x == 0) {
        const int total = sm[1023];
        if (b == 0) {
            atomicExch(&g_scan_pkt[0], (2ull << 32) | (unsigned)total);
            s_prefix = 0;
        } else {
            atomicExch(&g_scan_pkt[b], (1ull << 32) | (unsigned)total);
            int pfx = 0;
            int j = b - 1;
            while (true) {
                ull w;
                do { w = *(volatile ull*)&g_scan_pkt[j]; } while ((w >> 32) == 0);
                pfx += (int)(unsigned)w;
                if ((w >> 32) == 2ull) break;
                j--;
            }
            atomicExch(&g_scan_pkt[b], (2ull << 32) | (unsigned)(pfx + total));
            s_prefix = pfx;
        }
    }
    __syncthreads();
    const int pfx = s_prefix;
    if (i < N_NODES) {
        const int rp = pfx + incl - v;
        g_rowptr[i] = rp;
        g_cursor[i] = rp;
        g_dinv[i] = rsqrtf((float)(g_cnt[i] + 1));  // +1 self-loop
    }
    if (i == 0) g_rowptr[N_NODES] = N_EDGES;
}

__global__ void k_fill(const int* __restrict__ ei) {
    int e = blockIdx.x * blockDim.x + threadIdx.x;
    if (e < N_EDGES) {
        int src, dst;
        edge_fetch(ei, e, src, dst, g_is64);
        if ((unsigned)dst < N_NODES && (unsigned)src < N_NODES) {
            int pos = atomicAdd(&g_cursor[dst], 1);
            g_csr[pos] = src;
        }
    }
}

// ---------------- smem-staged tf32 GEMM: g_y16 = half((A @ W) * dinv) -------
// Block: 128 rows x 128 cols x K=128. 8 warps: warp = 32 rows x 64 cols.
// Operands staged in smem as pre-converted tf32; fragments via conflict-free LDS.
template <int SRC>
__global__ void __launch_bounds__(256) k_gemm_sm(
    const float* __restrict__ Ain, const float* __restrict__ W)
{
    const float* __restrict__ A = (SRC == 0) ? Ain : (const float*)g_h;

    extern __shared__ unsigned smem_u[];
    unsigned* sA = smem_u;                      // [128][SA_STRIDE]
    unsigned* sW = smem_u + 128 * SA_STRIDE;    // [128][SW_STRIDE]

    const int t = threadIdx.x;
    const int rb = blockIdx.x * 128;

    // stage W (128x128) coalesced float4, convert to tf32
#pragma unroll
    for (int p = 0; p < 16; p++) {
        int idx = p * 1024 + t * 4;
        int row = idx >> 7, col = idx & 127;
        float4 w4 = __ldg((const float4*)(W + (size_t)row * 128 + col));
        unsigned* d = sW + row * SW_STRIDE + col;
        d[0] = to_tf32(w4.x); d[1] = to_tf32(w4.y);
        d[2] = to_tf32(w4.z); d[3] = to_tf32(w4.w);
    }
    // stage A (block's 128 rows, clamped)
#pragma unroll
    for (int p = 0; p < 16; p++) {
        int idx = p * 1024 + t * 4;
        int row = idx >> 7, col = idx & 127;
        int g = rb + row; if (g >= N_NODES) g = N_NODES - 1;
        float4 a4 = __ldg((const float4*)(A + (size_t)g * 128 + col));
        unsigned* d = sA + row * SA_STRIDE + col;
        d[0] = to_tf32(a4.x); d[1] = to_tf32(a4.y);
        d[2] = to_tf32(a4.z); d[3] = to_tf32(a4.w);
    }
    __syncthreads();

    const int lane = t & 31;
    const int warp = t >> 5;
    const int m0w = (warp >> 1) * 32;   // local row base
    const int c0w = (warp & 1) * 64;    // col half
    const int qid = lane >> 2;
    const int t4 = lane & 3;

    float d[2][8][4];
#pragma unroll
    for (int mt = 0; mt < 2; mt++)
#pragma unroll
        for (int nt = 0; nt < 8; nt++)
#pragma unroll
            for (int i = 0; i < 4; i++) d[mt][nt][i] = 0.f;

#pragma unroll 2
    for (int it = 0; it < 16; it++) {
        const int k = it * 8;
        unsigned a[2][4];
#pragma unroll
        for (int mt = 0; mt < 2; mt++) {
            const int base = (m0w + mt * 16 + qid) * SA_STRIDE + k + t4;
            a[mt][0] = sA[base];
            a[mt][1] = sA[base + 8 * SA_STRIDE];
            a[mt][2] = sA[base + 4];
            a[mt][3] = sA[base + 8 * SA_STRIDE + 4];
        }
#pragma unroll
        for (int nt = 0; nt < 8; nt++) {
            const int wb = (k + t4) * SW_STRIDE + c0w + nt * 8 + qid;
            unsigned b0 = sW[wb];
            unsigned b1 = sW[wb + 4 * SW_STRIDE];
            mma_tf32(d[0][nt][0], d[0][nt][1], d[0][nt][2], d[0][nt][3],
                     a[0][0], a[0][1], a[0][2], a[0][3], b0, b1);
            mma_tf32(d[1][nt][0], d[1][nt][1], d[1][nt][2], d[1][nt][3],
                     a[1][0], a[1][1], a[1][2], a[1][3], b0, b1);
        }
    }

#pragma unroll
    for (int mt = 0; mt < 2; mt++) {
        const int row = rb + m0w + mt * 16 + qid;
        if (row < N_NODES) {
            const float s0 = g_dinv[row];
#pragma unroll
            for (int nt = 0; nt < 8; nt++) {
                const int col = c0w + nt * 8 + t4 * 2;
                *(__half2*)(g_y16 + (size_t)row * 128 + col) =
                    __floats2half2_rn(d[mt][nt][0] * s0, d[mt][nt][1] * s0);
            }
        }
        if (row + 8 < N_NODES) {
            const float s1 = g_dinv[row + 8];
#pragma unroll
            for (int nt = 0; nt < 8; nt++) {
                const int col = c0w + nt * 8 + t4 * 2;
                *(__half2*)(g_y16 + (size_t)(row + 8) * 128 + col) =
                    __floats2half2_rn(d[mt][nt][2] * s1, d[mt][nt][3] * s1);
            }
        }
    }
}

// ---------------- smem-staged FC head ----------------------------------------
// Block: 128 rows x 128 cols x K=144. 8 warps: warp = 16 rows x 128 cols.
// q = relu([g_h|action] @ fc1 + b1) . fc2 + b2   (fc2 fused in epilogue)
__global__ void __launch_bounds__(256) k_fc_sm(
    const float* __restrict__ act, const float* __restrict__ W,
    const float* __restrict__ bias, const float* __restrict__ w2,
    const float* __restrict__ w2b, float* __restrict__ out)
{
    extern __shared__ unsigned smem_u[];
    unsigned* sA = smem_u;                        // [128][SAFC_STRIDE]
    unsigned* sW = smem_u + 128 * SAFC_STRIDE;    // [144][SW_STRIDE]

    const int t = threadIdx.x;
    const int rb = blockIdx.x * 128;

    // stage W (144x128)
#pragma unroll
    for (int p = 0; p < 18; p++) {
        int idx = p * 1024 + t * 4;
        int row = idx >> 7, col = idx & 127;
        float4 w4 = __ldg((const float4*)(W + (size_t)row * 128 + col));
        unsigned* d = sW + row * SW_STRIDE + col;
        d[0] = to_tf32(w4.x); d[1] = to_tf32(w4.y);
        d[2] = to_tf32(w4.z); d[3] = to_tf32(w4.w);
    }
    // stage A cols 0..127 from g_h
#pragma unroll
    for (int p = 0; p < 16; p++) {
        int idx = p * 1024 + t * 4;
        int row = idx >> 7, col = idx & 127;
        int g = rb + row; if (g >= N_NODES) g = N_NODES - 1;
        float4 a4 = __ldg((const float4*)(g_h + (size_t)g * 128 + col));
        unsigned* d = sA + row * SAFC_STRIDE + col;
        d[0] = to_tf32(a4.x); d[1] = to_tf32(a4.y);
        d[2] = to_tf32(a4.z); d[3] = to_tf32(a4.w);
    }
    // stage A cols 128..143 from action (128 rows x 16 cols = 512 float4)
#pragma unroll
    for (int p = 0; p < 2; p++) {
        int fi = p * 256 + t;
        int row = fi >> 2, c4 = (fi & 3) * 4;
        int g = rb + row; if (g >= N_NODES) g = N_NODES - 1;
        float4 a4 = __ldg((const float4*)(act + (size_t)g * 16 + c4));
        unsigned* d = sA + row * SAFC_STRIDE + 128 + c4;
        d[0] = to_tf32(a4.x); d[1] = to_tf32(a4.y);
        d[2] = to_tf32(a4.z); d[3] = to_tf32(a4.w);
    }
    __syncthreads();

    const int lane = t & 31;
    const int warp = t >> 5;
    const int lr0 = warp * 16;          // local row base (16 rows per warp)
    const int qid = lane >> 2;
    const int t4 = lane & 3;

    float d[16][4];
#pragma unroll
    for (int nt = 0; nt < 16; nt++)
#pragma unroll
        for (int i = 0; i < 4; i++) d[nt][i] = 0.f;

#pragma unroll 2
    for (int kt = 0; kt < 18; kt++) {
        const int k = kt * 8;
        const int base = (lr0 + qid) * SAFC_STRIDE + k + t4;
        unsigned a0 = sA[base];
        unsigned a1 = sA[base + 8 * SAFC_STRIDE];
        unsigned a2 = sA[base + 4];
        unsigned a3 = sA[base + 8 * SAFC_STRIDE + 4];
#pragma unroll
        for (int nt = 0; nt < 16; nt++) {
            const int wb = (k + t4) * SW_STRIDE + nt * 8 + qid;
            unsigned b0 = sW[wb];
            unsigned b1 = sW[wb + 4 * SW_STRIDE];
            mma_tf32(d[nt][0], d[nt][1], d[nt][2], d[nt][3],
                     a0, a1, a2, a3, b0, b1);
        }
    }

    float plo = 0.f, phi = 0.f;
#pragma unroll
    for (int nt = 0; nt < 16; nt++) {
        const int col = nt * 8 + t4 * 2;
        float2 b2 = *(const float2*)(bias + col);
        float2 wv = *(const float2*)(w2 + col);
        plo += fmaxf(d[nt][0] + b2.x, 0.f) * wv.x + fmaxf(d[nt][1] + b2.y, 0.f) * wv.y;
        phi += fmaxf(d[nt][2] + b2.x, 0.f) * wv.x + fmaxf(d[nt][3] + b2.y, 0.f) * wv.y;
    }
    plo += __shfl_xor_sync(0xFFFFFFFFu, plo, 1);
    plo += __shfl_xor_sync(0xFFFFFFFFu, plo, 2);
    phi += __shfl_xor_sync(0xFFFFFFFFu, phi, 1);
    phi += __shfl_xor_sync(0xFFFFFFFFu, phi, 2);
    if (t4 == 0) {
        float ob = __ldg(w2b);
        int r0 = rb + lr0 + qid;
        if (r0 < N_NODES) out[r0] = plo + ob;
        if (r0 + 8 < N_NODES) out[r0 + 8] = phi + ob;
    }
}

// ---------------- gather-aggregate: one warp per dst row (fp16 y) -----------
__global__ void __launch_bounds__(256) k_aggregate(
    const float* __restrict__ bias)
{
    const int lane = threadIdx.x & 31;
    const int warp = threadIdx.x >> 5;
    const int row = blockIdx.x * 8 + warp;
    if (row >= N_NODES) return;

    const int s = g_rowptr[row];
    const int e = g_rowptr[row + 1];
    const uint2* yv = (const uint2*)g_y16;   // 4 halfs (8 B) per lane; row stride 32

    float4 a0, a1, a2, a3;
    {
        uint2 u = __ldg(&yv[(size_t)row * 32 + lane]);  // self-loop term
        float2 f0 = __half22float2(*(__half2*)&u.x);
        float2 f1 = __half22float2(*(__half2*)&u.y);
        a0 = make_float4(f0.x, f0.y, f1.x, f1.y);
    }
    a1 = make_float4(0.f, 0.f, 0.f, 0.f);
    a2 = a1; a3 = a1;

    int i = s;
    for (; i + 4 <= e; i += 4) {
        int i0 = g_csr[i + 0];
        int i1 = g_csr[i + 1];
        int i2 = g_csr[i + 2];
        int i3 = g_csr[i + 3];
        uint2 u0 = __ldg(&yv[(size_t)i0 * 32 + lane]);
        uint2 u1 = __ldg(&yv[(size_t)i1 * 32 + lane]);
        uint2 u2 = __ldg(&yv[(size_t)i2 * 32 + lane]);
        uint2 u3 = __ldg(&yv[(size_t)i3 * 32 + lane]);
        float2 f;
        f = __half22float2(*(__half2*)&u0.x); a0.x += f.x; a0.y += f.y;
        f = __half22float2(*(__half2*)&u0.y); a0.z += f.x; a0.w += f.y;
        f = __half22float2(*(__half2*)&u1.x); a1.x += f.x; a1.y += f.y;
        f = __half22float2(*(__half2*)&u1.y); a1.z += f.x; a1.w += f.y;
        f = __half22float2(*(__half2*)&u2.x); a2.x += f.x; a2.y += f.y;
        f = __half22float2(*(__half2*)&u2.y); a2.z += f.x; a2.w += f.y;
        f = __half22float2(*(__half2*)&u3.x); a3.x += f.x; a3.y += f.y;
        f = __half22float2(*(__half2*)&u3.y); a3.z += f.x; a3.w += f.y;
    }
    for (; i < e; i++) {
        int ix = g_csr[i];
        uint2 u = __ldg(&yv[(size_t)ix * 32 + lane]);
        float2 f;
        f = __half22float2(*(__half2*)&u.x); a0.x += f.x; a0.y += f.y;
        f = __half22float2(*(__half2*)&u.y); a0.z += f.x; a0.w += f.y;
    }
    float4 a = make_float4(a0.x + a1.x + a2.x + a3.x,
                           a0.y + a1.y + a2.y + a3.y,
                           a0.z + a1.z + a2.z + a3.z,
                           a0.w + a1.w + a2.w + a3.w);

    const float dv = g_dinv[row];
    float4 b4 = __ldg((const float4*)(bias + lane * 4));
    float4 o = make_float4(fmaxf(a.x * dv + b4.x, 0.f),
                           fmaxf(a.y * dv + b4.y, 0.f),
                           fmaxf(a.z * dv + b4.z, 0.f),
                           fmaxf(a.w * dv + b4.w, 0.f));
    *(float4*)(g_h + (size_t)row * 128 + lane * 4) = o;
}

// ---------------- launch ----------------------------------------------------
extern "C" void kernel_launch(void* const* d_in, const int* in_sizes, int n_in,
                              void* d_out, int out_size)
{
    const float* x      = (const float*)d_in[0];
    const int*   ei     = (const int*)d_in[1];   // int32 (JAX x64 off); detect guards int64
    const float* action = (const float*)d_in[2];
    const float* g1w    = (const float*)d_in[3];
    const float* g1b    = (const float*)d_in[4];
    const float* g2w    = (const float*)d_in[5];
    const float* g2b    = (const float*)d_in[6];
    const float* f1w    = (const float*)d_in[7];
    const float* f1b    = (const float*)d_in[8];
    const float* f2w    = (const float*)d_in[9];
    const float* f2b    = (const float*)d_in[10];
    float*       q      = (float*)d_out;

    // opt-in large dynamic smem (host-state only; enqueues nothing)
    cudaFuncSetAttribute(k_gemm_sm<0>, cudaFuncAttributeMaxDynamicSharedMemorySize, GEMM_SMEM);
    cudaFuncSetAttribute(k_gemm_sm<1>, cudaFuncAttributeMaxDynamicSharedMemorySize, GEMM_SMEM);
    cudaFuncSetAttribute(k_fc_sm,      cudaFuncAttributeMaxDynamicSharedMemorySize, FC_SMEM);

    const int agg_grid = (N_NODES + 7) / 8;

    // CSR build (gemm1 kept at slot 3 for the ncu window)
    k_detect_init<<<SCAN_BLOCKS, 1024>>>(ei);                       // 0
    k_hist<<<(N_EDGES + 255) / 256, 256>>>(ei);                     // 1
    k_scan<<<SCAN_BLOCKS, 1024>>>();                                // 2
    k_gemm_sm<0><<<GEMM_BLOCKS, 256, GEMM_SMEM>>>(x, g1w);          // 3  <- profiled
    k_fill<<<(N_EDGES + 255) / 256, 256>>>(ei);                     // 4

    // Layer 1 aggregate
    k_aggregate<<<agg_grid, 256>>>(g1b);                            // 5

    // Layer 2
    k_gemm_sm<1><<<GEMM_BLOCKS, 256, GEMM_SMEM>>>(nullptr, g2w);    // 6
    k_aggregate<<<agg_grid, 256>>>(g2b);                            // 7

    // FC head (tensor-core, fc2 fused)
    k_fc_sm<<<GEMM_BLOCKS, 256, FC_SMEM>>>(action, f1w, f1b, f2w, f2b, q);  // 8
}

// round 10
// speedup vs baseline: 3.4059x; 1.0816x over previous
#include <cuda_runtime.h>
#include <cuda_fp16.h>

#define N_NODES 100000
#define N_EDGES 1600000
#define SCAN_BLOCKS 98    // ceil(100000/1024)
#define GEMM_BLOCKS 391   // ceil(100000/256)
#define FC_BLOCKS 782     // ceil(100000/128)

// GEMM smem (fp32 words): double-buffered K-chunks
#define SA_STRIDE 36         // 32 + 4 pad  -> frag bank (4*qid + t4) conflict-free
#define SW_STRIDE 136        // 128 + 8 pad -> frag bank (8*t4 + qid) conflict-free
#define SA_BUF (256 * SA_STRIDE)          // 9216 words per buffer
#define SW_BUF (32 * SW_STRIDE)           // 4352 words per buffer
#define GEMM_SMEM ((2 * SA_BUF + 2 * SW_BUF) * 4)   // 108544 B

// FC smem (tf32 words, single-stage as in R9)
#define SAFC_STRIDE 148
#define SWFC_STRIDE 136
#define FC_SMEM ((128 * SAFC_STRIDE + 144 * SWFC_STRIDE) * 4)  // 154112 B

typedef unsigned long long ull;

// ---------------- scratch (static __device__ allocations; no cudaMalloc) ----
__device__ __half g_y16[(size_t)N_NODES * 128];  // (A@W)*dinv buffer (fp16)
__device__ float  g_h[(size_t)N_NODES * 128];    // post-aggregate hidden buffer
__device__ int    g_cnt[N_NODES];
__device__ int    g_rowptr[N_NODES + 1];
__device__ int    g_cursor[N_NODES];
__device__ float  g_dinv[N_NODES];
__device__ int    g_csr[N_EDGES];
__device__ ull    g_scan_pkt[SCAN_BLOCKS];       // (flag<<32) | value
__device__ int    g_is64;

// ---------------- helpers ---------------------------------------------------
__device__ __forceinline__ unsigned to_tf32(float x) {
    unsigned r;
    asm("cvt.rna.tf32.f32 %0, %1;" : "=r"(r) : "f"(x));
    return r;
}

__device__ __forceinline__ void mma_tf32(
    float& d0, float& d1, float& d2, float& d3,
    unsigned a0, unsigned a1, unsigned a2, unsigned a3,
    unsigned b0, unsigned b1)
{
    asm("mma.sync.aligned.m16n8k8.row.col.f32.tf32.tf32.f32 "
        "{%0,%1,%2,%3}, {%4,%5,%6,%7}, {%8,%9}, {%0,%1,%2,%3};"
        : "+f"(d0), "+f"(d1), "+f"(d2), "+f"(d3)
        : "r"(a0), "r"(a1), "r"(a2), "r"(a3), "r"(b0), "r"(b1));
}

__device__ __forceinline__ void cp_async16(void* smem_dst, const void* gsrc) {
    unsigned saddr = (unsigned)__cvta_generic_to_shared(smem_dst);
    asm volatile("cp.async.ca.shared.global [%0], [%1], 16;"
                 :: "r"(saddr), "l"(gsrc));
}
__device__ __forceinline__ void cp_commit() {
    asm volatile("cp.async.commit_group;");
}
template <int N>
__device__ __forceinline__ void cp_wait() {
    asm volatile("cp.async.wait_group %0;" :: "n"(N));
}

__device__ __forceinline__ void edge_fetch(const int* __restrict__ ei, int e,
                                           int& src, int& dst, int is64) {
    if (is64) {
        src = ei[2 * e];
        dst = ei[2 * (N_EDGES + e)];
    } else {
        src = ei[e];
        dst = ei[N_EDGES + e];
    }
}

// ---------------- init + dtype detection (fused) -----------------------------
__global__ void k_detect_init(const int* __restrict__ ei) {
    int i = blockIdx.x * blockDim.x + threadIdx.x;
    if (i < N_NODES) g_cnt[i] = 0;
    if (i < SCAN_BLOCKS) g_scan_pkt[i] = 0ull;
    if (i == 0) {
        int acc = 0;
        for (int j = 0; j < 64; j++) acc |= ei[2 * j + 1];
        g_is64 = (acc == 0) ? 1 : 0;
    }
}

__global__ void k_hist(const int* __restrict__ ei) {
    int e = blockIdx.x * blockDim.x + threadIdx.x;
    if (e < N_EDGES) {
        int src, dst;
        edge_fetch(ei, e, src, dst, g_is64);
        if ((unsigned)dst < N_NODES) atomicAdd(&g_cnt[dst], 1);
    }
}

// ---------------- single-pass scan (decoupled lookback) + rowptr/dinv --------
__global__ void __launch_bounds__(1024) k_scan() {
    __shared__ int sm[1024];
    __shared__ int s_prefix;
    const int b = blockIdx.x;
    const int i = b * 1024 + threadIdx.x;
    const int v = (i < N_NODES) ? g_cnt[i] : 0;
    sm[threadIdx.x] = v;
    __syncthreads();
#pragma unroll
    for (int off = 1; off < 1024; off <<= 1) {
        int t = (threadIdx.x >= off) ? sm[threadIdx.x - off] : 0;
        __syncthreads();
        sm[threadIdx.x] += t;
        __syncthreads();
    }
    const int incl = sm[threadIdx.x];

    if (threadIdx.x == 0) {
        const int total = sm[1023];
        if (b == 0) {
            atomicExch(&g_scan_pkt[0], (2ull << 32) | (unsigned)total);
            s_prefix = 0;
        } else {
            atomicExch(&g_scan_pkt[b], (1ull << 32) | (unsigned)total);
            int pfx = 0;
            int j = b - 1;
            while (true) {
                ull w;
                do { w = *(volatile ull*)&g_scan_pkt[j]; } while ((w >> 32) == 0);
                pfx += (int)(unsigned)w;
                if ((w >> 32) == 2ull) break;
                j--;
            }
            atomicExch(&g_scan_pkt[b], (2ull << 32) | (unsigned)(pfx + total));
            s_prefix = pfx;
        }
    }
    __syncthreads();
    const int pfx = s_prefix;
    if (i < N_NODES) {
        const int rp = pfx + incl - v;
        g_rowptr[i] = rp;
        g_cursor[i] = rp;
        g_dinv[i] = rsqrtf((float)(g_cnt[i] + 1));  // +1 self-loop
    }
    if (i == 0) g_rowptr[N_NODES] = N_EDGES;
}

__global__ void k_fill(const int* __restrict__ ei) {
    int e = blockIdx.x * blockDim.x + threadIdx.x;
    if (e < N_EDGES) {
        int src, dst;
        edge_fetch(ei, e, src, dst, g_is64);
        if ((unsigned)dst < N_NODES && (unsigned)src < N_NODES) {
            int pos = atomicAdd(&g_cursor[dst], 1);
            g_csr[pos] = src;
        }
    }
}

// ---------------- cp.async double-buffered tf32 GEMM ------------------------
// Block: 256 rows x 128 cols, 512 threads (16 warps of 32x64 tile).
// K split into 4 chunks of 32, double-buffered via cp.async.
template <int SRC>
__global__ void __launch_bounds__(512, 1) k_gemm_cp(
    const float* __restrict__ Ain, const float* __restrict__ W)
{
    const float* __restrict__ A = (SRC == 0) ? Ain : (const float*)g_h;

    extern __shared__ float smem_f[];
    float* sA = smem_f;                 // [2][256][SA_STRIDE]
    float* sW = smem_f + 2 * SA_BUF;    // [2][32][SW_STRIDE]

    const int t = threadIdx.x;
    const int rb = blockIdx.x * 256;

    // stage chunk -> buffer buf
    auto stage = [&](int chunk, int buf) {
        // A: 256 rows x 32 floats (128 B/row) = 2048 x 16B ops, 4 per thread
#pragma unroll
        for (int p = 0; p < 4; p++) {
            int idx = p * 512 + t;
            int row = idx >> 3, seg = idx & 7;
            int g = rb + row; if (g >= N_NODES) g = N_NODES - 1;
            cp_async16(sA + buf * SA_BUF + row * SA_STRIDE + seg * 4,
                       A + (size_t)g * 128 + chunk * 32 + seg * 4);
        }
        // W: 32 rows x 128 floats = 1024 x 16B ops, 2 per thread
#pragma unroll
        for (int p = 0; p < 2; p++) {
            int idx = p * 512 + t;
            int row = idx >> 5, seg = idx & 31;
            cp_async16(sW + buf * SW_BUF + row * SW_STRIDE + seg * 4,
                       W + (size_t)(chunk * 32 + row) * 128 + seg * 4);
        }
        cp_commit();
    };

    const int lane = t & 31;
    const int warp = t >> 5;
    const int m0w = (warp >> 1) * 32;   // local row base (8 stripes x 32)
    const int c0w = (warp & 1) * 64;    // col half
    const int qid = lane >> 2;
    const int t4 = lane & 3;

    float d[2][8][4];
#pragma unroll
    for (int mt = 0; mt < 2; mt++)
#pragma unroll
        for (int nt = 0; nt < 8; nt++)
#pragma unroll
            for (int i = 0; i < 4; i++) d[mt][nt][i] = 0.f;

    stage(0, 0);

#pragma unroll
    for (int c = 0; c < 4; c++) {
        if (c < 3) stage(c + 1, (c + 1) & 1);
        if (c < 3) cp_wait<1>(); else cp_wait<0>();
        __syncthreads();

        const float* cA = sA + (c & 1) * SA_BUF;
        const float* cW = sW + (c & 1) * SW_BUF;
#pragma unroll
        for (int it = 0; it < 4; it++) {
            const int k = it * 8;
            unsigned a[2][4];
#pragma unroll
            for (int mt = 0; mt < 2; mt++) {
                const int base = (m0w + mt * 16 + qid) * SA_STRIDE + k + t4;
                a[mt][0] = to_tf32(cA[base]);
                a[mt][1] = to_tf32(cA[base + 8 * SA_STRIDE]);
                a[mt][2] = to_tf32(cA[base + 4]);
                a[mt][3] = to_tf32(cA[base + 8 * SA_STRIDE + 4]);
            }
#pragma unroll
            for (int nt = 0; nt < 8; nt++) {
                const int wb = (k + t4) * SW_STRIDE + c0w + nt * 8 + qid;
                unsigned b0 = to_tf32(cW[wb]);
                unsigned b1 = to_tf32(cW[wb + 4 * SW_STRIDE]);
                mma_tf32(d[0][nt][0], d[0][nt][1], d[0][nt][2], d[0][nt][3],
                         a[0][0], a[0][1], a[0][2], a[0][3], b0, b1);
                mma_tf32(d[1][nt][0], d[1][nt][1], d[1][nt][2], d[1][nt][3],
                         a[1][0], a[1][1], a[1][2], a[1][3], b0, b1);
            }
        }
        __syncthreads();
    }

#pragma unroll
    for (int mt = 0; mt < 2; mt++) {
        const int row = rb + m0w + mt * 16 + qid;
        if (row < N_NODES) {
            const float s0 = g_dinv[row];
#pragma unroll
            for (int nt = 0; nt < 8; nt++) {
                const int col = c0w + nt * 8 + t4 * 2;
                *(__half2*)(g_y16 + (size_t)row * 128 + col) =
                    __floats2half2_rn(d[mt][nt][0] * s0, d[mt][nt][1] * s0);
            }
        }
        if (row + 8 < N_NODES) {
            const float s1 = g_dinv[row + 8];
#pragma unroll
            for (int nt = 0; nt < 8; nt++) {
                const int col = c0w + nt * 8 + t4 * 2;
                *(__half2*)(g_y16 + (size_t)(row + 8) * 128 + col) =
                    __floats2half2_rn(d[mt][nt][2] * s1, d[mt][nt][3] * s1);
            }
        }
    }
}

// ---------------- smem-staged FC head (R9, unchanged) ------------------------
__global__ void __launch_bounds__(256) k_fc_sm(
    const float* __restrict__ act, const float* __restrict__ W,
    const float* __restrict__ bias, const float* __restrict__ w2,
    const float* __restrict__ w2b, float* __restrict__ out)
{
    extern __shared__ unsigned smem_u[];
    unsigned* sA = smem_u;                        // [128][SAFC_STRIDE]
    unsigned* sW = smem_u + 128 * SAFC_STRIDE;    // [144][SWFC_STRIDE]

    const int t = threadIdx.x;
    const int rb = blockIdx.x * 128;

#pragma unroll
    for (int p = 0; p < 18; p++) {
        int idx = p * 1024 + t * 4;
        int row = idx >> 7, col = idx & 127;
        float4 w4 = __ldg((const float4*)(W + (size_t)row * 128 + col));
        unsigned* d = sW + row * SWFC_STRIDE + col;
        d[0] = to_tf32(w4.x); d[1] = to_tf32(w4.y);
        d[2] = to_tf32(w4.z); d[3] = to_tf32(w4.w);
    }
#pragma unroll
    for (int p = 0; p < 16; p++) {
        int idx = p * 1024 + t * 4;
        int row = idx >> 7, col = idx & 127;
        int g = rb + row; if (g >= N_NODES) g = N_NODES - 1;
        float4 a4 = __ldg((const float4*)(g_h + (size_t)g * 128 + col));
        unsigned* d = sA + row * SAFC_STRIDE + col;
        d[0] = to_tf32(a4.x); d[1] = to_tf32(a4.y);
        d[2] = to_tf32(a4.z); d[3] = to_tf32(a4.w);
    }
#pragma unroll
    for (int p = 0; p < 2; p++) {
        int fi = p * 256 + t;
        int row = fi >> 2, c4 = (fi & 3) * 4;
        int g = rb + row; if (g >= N_NODES) g = N_NODES - 1;
        float4 a4 = __ldg((const float4*)(act + (size_t)g * 16 + c4));
        unsigned* d = sA + row * SAFC_STRIDE + 128 + c4;
        d[0] = to_tf32(a4.x); d[1] = to_tf32(a4.y);
        d[2] = to_tf32(a4.z); d[3] = to_tf32(a4.w);
    }
    __syncthreads();

    const int lane = t & 31;
    const int warp = t >> 5;
    const int lr0 = warp * 16;
    const int qid = lane >> 2;
    const int t4 = lane & 3;

    float d[16][4];
#pragma unroll
    for (int nt = 0; nt < 16; nt++)
#pragma unroll
        for (int i = 0; i < 4; i++) d[nt][i] = 0.f;

#pragma unroll 2
    for (int kt = 0; kt < 18; kt++) {
        const int k = kt * 8;
        const int base = (lr0 + qid) * SAFC_STRIDE + k + t4;
        unsigned a0 = sA[base];
        unsigned a1 = sA[base + 8 * SAFC_STRIDE];
        unsigned a2 = sA[base + 4];
        unsigned a3 = sA[base + 8 * SAFC_STRIDE + 4];
#pragma unroll
        for (int nt = 0; nt < 16; nt++) {
            const int wb = (k + t4) * SWFC_STRIDE + nt * 8 + qid;
            unsigned b0 = sW[wb];
            unsigned b1 = sW[wb + 4 * SWFC_STRIDE];
            mma_tf32(d[nt][0], d[nt][1], d[nt][2], d[nt][3],
                     a0, a1, a2, a3, b0, b1);
        }
    }

    float plo = 0.f, phi = 0.f;
#pragma unroll
    for (int nt = 0; nt < 16; nt++) {
        const int col = nt * 8 + t4 * 2;
        float2 b2 = *(const float2*)(bias + col);
        float2 wv = *(const float2*)(w2 + col);
        plo += fmaxf(d[nt][0] + b2.x, 0.f) * wv.x + fmaxf(d[nt][1] + b2.y, 0.f) * wv.y;
        phi += fmaxf(d[nt][2] + b2.x, 0.f) * wv.x + fmaxf(d[nt][3] + b2.y, 0.f) * wv.y;
    }
    plo += __shfl_xor_sync(0xFFFFFFFFu, plo, 1);
    plo += __shfl_xor_sync(0xFFFFFFFFu, plo, 2);
    phi += __shfl_xor_sync(0xFFFFFFFFu, phi, 1);
    phi += __shfl_xor_sync(0xFFFFFFFFu, phi, 2);
    if (t4 == 0) {
        float ob = __ldg(w2b);
        int r0 = rb + lr0 + qid;
        if (r0 < N_NODES) out[r0] = plo + ob;
        if (r0 + 8 < N_NODES) out[r0 + 8] = phi + ob;
    }
}

// ---------------- gather-aggregate: one warp per dst row (fp16 y) -----------
__global__ void __launch_bounds__(256) k_aggregate(
    const float* __restrict__ bias)
{
    const int lane = threadIdx.x & 31;
    const int warp = threadIdx.x >> 5;
    const int row = blockIdx.x * 8 + warp;
    if (row >= N_NODES) return;

    const int s = g_rowptr[row];
    const int e = g_rowptr[row + 1];
    const uint2* yv = (const uint2*)g_y16;

    float4 a0, a1, a2, a3;
    {
        uint2 u = __ldg(&yv[(size_t)row * 32 + lane]);
        float2 f0 = __half22float2(*(__half2*)&u.x);
        float2 f1 = __half22float2(*(__half2*)&u.y);
        a0 = make_float4(f0.x, f0.y, f1.x, f1.y);
    }
    a1 = make_float4(0.f, 0.f, 0.f, 0.f);
    a2 = a1; a3 = a1;

    int i = s;
    for (; i + 4 <= e; i += 4) {
        int i0 = g_csr[i + 0];
        int i1 = g_csr[i + 1];
        int i2 = g_csr[i + 2];
        int i3 = g_csr[i + 3];
        uint2 u0 = __ldg(&yv[(size_t)i0 * 32 + lane]);
        uint2 u1 = __ldg(&yv[(size_t)i1 * 32 + lane]);
        uint2 u2 = __ldg(&yv[(size_t)i2 * 32 + lane]);
        uint2 u3 = __ldg(&yv[(size_t)i3 * 32 + lane]);
        float2 f;
        f = __half22float2(*(__half2*)&u0.x); a0.x += f.x; a0.y += f.y;
        f = __half22float2(*(__half2*)&u0.y); a0.z += f.x; a0.w += f.y;
        f = __half22float2(*(__half2*)&u1.x); a1.x += f.x; a1.y += f.y;
        f = __half22float2(*(__half2*)&u1.y); a1.z += f.x; a1.w += f.y;
        f = __half22float2(*(__half2*)&u2.x); a2.x += f.x; a2.y += f.y;
        f = __half22float2(*(__half2*)&u2.y); a2.z += f.x; a2.w += f.y;
        f = __half22float2(*(__half2*)&u3.x); a3.x += f.x; a3.y += f.y;
        f = __half22float2(*(__half2*)&u3.y); a3.z += f.x; a3.w += f.y;
    }
    for (; i < e; i++) {
        int ix = g_csr[i];
        uint2 u = __ldg(&yv[(size_t)ix * 32 + lane]);
        float2 f;
        f = __half22float2(*(__half2*)&u.x); a0.x += f.x; a0.y += f.y;
        f = __half22float2(*(__half2*)&u.y); a0.z += f.x; a0.w += f.y;
    }
    float4 a = make_float4(a0.x + a1.x + a2.x + a3.x,
                           a0.y + a1.y + a2.y + a3.y,
                           a0.z + a1.z + a2.z + a3.z,
                           a0.w + a1.w + a2.w + a3.w);

    const float dv = g_dinv[row];
    float4 b4 = __ldg((const float4*)(bias + lane * 4));
    float4 o = make_float4(fmaxf(a.x * dv + b4.x, 0.f),
                           fmaxf(a.y * dv + b4.y, 0.f),
                           fmaxf(a.z * dv + b4.z, 0.f),
                           fmaxf(a.w * dv + b4.w, 0.f));
    *(float4*)(g_h + (size_t)row * 128 + lane * 4) = o;
}

// ---------------- launch ----------------------------------------------------
extern "C" void kernel_launch(void* const* d_in, const int* in_sizes, int n_in,
                              void* d_out, int out_size)
{
    const float* x      = (const float*)d_in[0];
    const int*   ei     = (const int*)d_in[1];
    const float* action = (const float*)d_in[2];
    const float* g1w    = (const float*)d_in[3];
    const float* g1b    = (const float*)d_in[4];
    const float* g2w    = (const float*)d_in[5];
    const float* g2b    = (const float*)d_in[6];
    const float* f1w    = (const float*)d_in[7];
    const float* f1b    = (const float*)d_in[8];
    const float* f2w    = (const float*)d_in[9];
    const float* f2b    = (const float*)d_in[10];
    float*       q      = (float*)d_out;

    cudaFuncSetAttribute(k_gemm_cp<0>, cudaFuncAttributeMaxDynamicSharedMemorySize, GEMM_SMEM);
    cudaFuncSetAttribute(k_gemm_cp<1>, cudaFuncAttributeMaxDynamicSharedMemorySize, GEMM_SMEM);
    cudaFuncSetAttribute(k_fc_sm,      cudaFuncAttributeMaxDynamicSharedMemorySize, FC_SMEM);

    const int agg_grid = (N_NODES + 7) / 8;

    // CSR build (gemm1 kept at slot 3 for the ncu window)
    k_detect_init<<<SCAN_BLOCKS, 1024>>>(ei);                       // 0
    k_hist<<<(N_EDGES + 255) / 256, 256>>>(ei);                     // 1
    k_scan<<<SCAN_BLOCKS, 1024>>>();                                // 2
    k_gemm_cp<0><<<GEMM_BLOCKS, 512, GEMM_SMEM>>>(x, g1w);          // 3  <- profiled
    k_fill<<<(N_EDGES + 255) / 256, 256>>>(ei);                     // 4

    k_aggregate<<<agg_grid, 256>>>(g1b);                            // 5

    k_gemm_cp<1><<<GEMM_BLOCKS, 512, GEMM_SMEM>>>(nullptr, g2w);    // 6
    k_aggregate<<<agg_grid, 256>>>(g2b);                            // 7

    k_fc_sm<<<FC_BLOCKS, 256, FC_SMEM>>>(action, f1w, f1b, f2w, f2b, q);  // 8
}

// round 11
// speedup vs baseline: 3.7939x; 1.1139x over previous
#include <cuda_runtime.h>
#include <cuda_fp16.h>

#define N_NODES 100000
#define N_EDGES 1600000
#define SCAN_BLOCKS 98    // ceil(100000/1024)
#define GEMM_BLOCKS 391   // ceil(100000/256)

// GEMM smem (fp32 words): double-buffered K-chunks
#define SA_STRIDE 36         // 32 + 4 pad  -> frag bank (4*qid + t4) conflict-free
#define SW_STRIDE 136        // 128 + 8 pad -> frag bank (8*t4 + qid) conflict-free
#define SA_BUF (256 * SA_STRIDE)          // 9216 words per buffer
#define SW_BUF (32 * SW_STRIDE)           // 4352 words per buffer
#define GEMM_SMEM ((2 * SA_BUF + 2 * SW_BUF) * 4)   // 108544 B

typedef unsigned long long ull;

// ---------------- scratch (static __device__ allocations; no cudaMalloc) ----
__device__ __half g_y16[(size_t)N_NODES * 128];  // (A@W)*dinv buffer (fp16)
__device__ float  g_h[(size_t)N_NODES * 128];    // post-aggregate hidden buffer
__device__ int    g_cnt[N_NODES];
__device__ int    g_rowptr[N_NODES + 1];
__device__ int    g_cursor[N_NODES];
__device__ float  g_dinv[N_NODES];
__device__ int    g_csr[N_EDGES];
__device__ ull    g_scan_pkt[SCAN_BLOCKS];       // (flag<<32) | value
__device__ int    g_is64;

// ---------------- helpers ---------------------------------------------------
// tf32 mma consuming RAW fp32 bit patterns (HW truncates to tf32 = RZ).
__device__ __forceinline__ void mma_tf32(
    float& d0, float& d1, float& d2, float& d3,
    unsigned a0, unsigned a1, unsigned a2, unsigned a3,
    unsigned b0, unsigned b1)
{
    asm("mma.sync.aligned.m16n8k8.row.col.f32.tf32.tf32.f32 "
        "{%0,%1,%2,%3}, {%4,%5,%6,%7}, {%8,%9}, {%0,%1,%2,%3};"
        : "+f"(d0), "+f"(d1), "+f"(d2), "+f"(d3)
        : "r"(a0), "r"(a1), "r"(a2), "r"(a3), "r"(b0), "r"(b1));
}

__device__ __forceinline__ void cp_async16(void* smem_dst, const void* gsrc) {
    unsigned saddr = (unsigned)__cvta_generic_to_shared(smem_dst);
    asm volatile("cp.async.ca.shared.global [%0], [%1], 16;"
                 :: "r"(saddr), "l"(gsrc));
}
__device__ __forceinline__ void cp_commit() {
    asm volatile("cp.async.commit_group;");
}
template <int N>
__device__ __forceinline__ void cp_wait() {
    asm volatile("cp.async.wait_group %0;" :: "n"(N));
}

__device__ __forceinline__ void edge_fetch(const int* __restrict__ ei, int e,
                                           int& src, int& dst, int is64) {
    if (is64) {
        src = ei[2 * e];
        dst = ei[2 * (N_EDGES + e)];
    } else {
        src = ei[e];
        dst = ei[N_EDGES + e];
    }
}

// ---------------- init + dtype detection (fused) -----------------------------
__global__ void k_detect_init(const int* __restrict__ ei) {
    int i = blockIdx.x * blockDim.x + threadIdx.x;
    if (i < N_NODES) g_cnt[i] = 0;
    if (i < SCAN_BLOCKS) g_scan_pkt[i] = 0ull;
    if (i == 0) {
        int acc = 0;
        for (int j = 0; j < 64; j++) acc |= ei[2 * j + 1];
        g_is64 = (acc == 0) ? 1 : 0;
    }
}

__global__ void k_hist(const int* __restrict__ ei) {
    int e = blockIdx.x * blockDim.x + threadIdx.x;
    if (e < N_EDGES) {
        int src, dst;
        edge_fetch(ei, e, src, dst, g_is64);
        if ((unsigned)dst < N_NODES) atomicAdd(&g_cnt[dst], 1);
    }
}

// ---------------- single-pass scan (decoupled lookback) + rowptr/dinv --------
__global__ void __launch_bounds__(1024) k_scan() {
    __shared__ int sm[1024];
    __shared__ int s_prefix;
    const int b = blockIdx.x;
    const int i = b * 1024 + threadIdx.x;
    const int v = (i < N_NODES) ? g_cnt[i] : 0;
    sm[threadIdx.x] = v;
    __syncthreads();
#pragma unroll
    for (int off = 1; off < 1024; off <<= 1) {
        int t = (threadIdx.x >= off) ? sm[threadIdx.x - off] : 0;
        __syncthreads();
        sm[threadIdx.x] += t;
        __syncthreads();
    }
    const int incl = sm[threadIdx.x];

    if (threadIdx.x == 0) {
        const int total = sm[1023];
        if (b == 0) {
            atomicExch(&g_scan_pkt[0], (2ull << 32) | (unsigned)total);
            s_prefix = 0;
        } else {
            atomicExch(&g_scan_pkt[b], (1ull << 32) | (unsigned)total);
            int pfx = 0;
            int j = b - 1;
            while (true) {
                ull w;
                do { w = *(volatile ull*)&g_scan_pkt[j]; } while ((w >> 32) == 0);
                pfx += (int)(unsigned)w;
                if ((w >> 32) == 2ull) break;
                j--;
            }
            atomicExch(&g_scan_pkt[b], (2ull << 32) | (unsigned)(pfx + total));
            s_prefix = pfx;
        }
    }
    __syncthreads();
    const int pfx = s_prefix;
    if (i < N_NODES) {
        const int rp = pfx + incl - v;
        g_rowptr[i] = rp;
        g_cursor[i] = rp;
        g_dinv[i] = rsqrtf((float)(g_cnt[i] + 1));  // +1 self-loop
    }
    if (i == 0) g_rowptr[N_NODES] = N_EDGES;
}

__global__ void k_fill(const int* __restrict__ ei) {
    int e = blockIdx.x * blockDim.x + threadIdx.x;
    if (e < N_EDGES) {
        int src, dst;
        edge_fetch(ei, e, src, dst, g_is64);
        if ((unsigned)dst < N_NODES && (unsigned)src < N_NODES) {
            int pos = atomicAdd(&g_cursor[dst], 1);
            g_csr[pos] = src;
        }
    }
}

// ---------------- cp.async double-buffered tf32 GEMM ------------------------
// Block: 256 rows x 128 cols, 512 threads (16 warps of 32x64 tile).
// K split into 4 chunks of 32, double-buffered via cp.async. Raw fp32 -> mma.
template <int SRC>
__global__ void __launch_bounds__(512, 1) k_gemm_cp(
    const float* __restrict__ Ain, const float* __restrict__ W)
{
    const float* __restrict__ A = (SRC == 0) ? Ain : (const float*)g_h;

    extern __shared__ float smem_f[];
    float* sA = smem_f;                 // [2][256][SA_STRIDE]
    float* sW = smem_f + 2 * SA_BUF;    // [2][32][SW_STRIDE]

    const int t = threadIdx.x;
    const int rb = blockIdx.x * 256;

    auto stage = [&](int chunk, int buf) {
#pragma unroll
        for (int p = 0; p < 4; p++) {
            int idx = p * 512 + t;
            int row = idx >> 3, seg = idx & 7;
            int g = rb + row; if (g >= N_NODES) g = N_NODES - 1;
            cp_async16(sA + buf * SA_BUF + row * SA_STRIDE + seg * 4,
                       A + (size_t)g * 128 + chunk * 32 + seg * 4);
        }
#pragma unroll
        for (int p = 0; p < 2; p++) {
            int idx = p * 512 + t;
            int row = idx >> 5, seg = idx & 31;
            cp_async16(sW + buf * SW_BUF + row * SW_STRIDE + seg * 4,
                       W + (size_t)(chunk * 32 + row) * 128 + seg * 4);
        }
        cp_commit();
    };

    const int lane = t & 31;
    const int warp = t >> 5;
    const int m0w = (warp >> 1) * 32;
    const int c0w = (warp & 1) * 64;
    const int qid = lane >> 2;
    const int t4 = lane & 3;

    float d[2][8][4];
#pragma unroll
    for (int mt = 0; mt < 2; mt++)
#pragma unroll
        for (int nt = 0; nt < 8; nt++)
#pragma unroll
            for (int i = 0; i < 4; i++) d[mt][nt][i] = 0.f;

    stage(0, 0);

#pragma unroll
    for (int c = 0; c < 4; c++) {
        if (c < 3) stage(c + 1, (c + 1) & 1);
        if (c < 3) cp_wait<1>(); else cp_wait<0>();
        __syncthreads();

        const unsigned* cA = (const unsigned*)(sA + (c & 1) * SA_BUF);
        const unsigned* cW = (const unsigned*)(sW + (c & 1) * SW_BUF);
#pragma unroll
        for (int it = 0; it < 4; it++) {
            const int k = it * 8;
            unsigned a[2][4];
#pragma unroll
            for (int mt = 0; mt < 2; mt++) {
                const int base = (m0w + mt * 16 + qid) * SA_STRIDE + k + t4;
                a[mt][0] = cA[base];
                a[mt][1] = cA[base + 8 * SA_STRIDE];
                a[mt][2] = cA[base + 4];
                a[mt][3] = cA[base + 8 * SA_STRIDE + 4];
            }
#pragma unroll
            for (int nt = 0; nt < 8; nt++) {
                const int wb = (k + t4) * SW_STRIDE + c0w + nt * 8 + qid;
                unsigned b0 = cW[wb];
                unsigned b1 = cW[wb + 4 * SW_STRIDE];
                mma_tf32(d[0][nt][0], d[0][nt][1], d[0][nt][2], d[0][nt][3],
                         a[0][0], a[0][1], a[0][2], a[0][3], b0, b1);
                mma_tf32(d[1][nt][0], d[1][nt][1], d[1][nt][2], d[1][nt][3],
                         a[1][0], a[1][1], a[1][2], a[1][3], b0, b1);
            }
        }
        __syncthreads();
    }

#pragma unroll
    for (int mt = 0; mt < 2; mt++) {
        const int row = rb + m0w + mt * 16 + qid;
        if (row < N_NODES) {
            const float s0 = g_dinv[row];
#pragma unroll
            for (int nt = 0; nt < 8; nt++) {
                const int col = c0w + nt * 8 + t4 * 2;
                *(__half2*)(g_y16 + (size_t)row * 128 + col) =
                    __floats2half2_rn(d[mt][nt][0] * s0, d[mt][nt][1] * s0);
            }
        }
        if (row + 8 < N_NODES) {
            const float s1 = g_dinv[row + 8];
#pragma unroll
            for (int nt = 0; nt < 8; nt++) {
                const int col = c0w + nt * 8 + t4 * 2;
                *(__half2*)(g_y16 + (size_t)(row + 8) * 128 + col) =
                    __floats2half2_rn(d[mt][nt][2] * s1, d[mt][nt][3] * s1);
            }
        }
    }
}

// ---------------- cp.async FC head ------------------------------------------
// Same skeleton; K=144 = 4x32 chunks (g_h, W rows 0..127) + 1x16 tail (action,
// W rows 128..143). Epilogue: relu(+b1), dot fc2 over own 64 cols, quad-reduce,
// cross-warp-pair combine via smem scratch. q = ... + b2.
__global__ void __launch_bounds__(512, 1) k_fc_cp(
    const float* __restrict__ act, const float* __restrict__ W,
    const float* __restrict__ bias, const float* __restrict__ w2,
    const float* __restrict__ w2b, float* __restrict__ out)
{
    extern __shared__ float smem_f[];
    float* sA = smem_f;                 // [2][256][SA_STRIDE]
    float* sW = smem_f + 2 * SA_BUF;    // [2][32][SW_STRIDE]

    const int t = threadIdx.x;
    const int rb = blockIdx.x * 256;

    auto stage_main = [&](int chunk, int buf) {
#pragma unroll
        for (int p = 0; p < 4; p++) {
            int idx = p * 512 + t;
            int row = idx >> 3, seg = idx & 7;
            int g = rb + row; if (g >= N_NODES) g = N_NODES - 1;
            cp_async16(sA + buf * SA_BUF + row * SA_STRIDE + seg * 4,
                       g_h + (size_t)g * 128 + chunk * 32 + seg * 4);
        }
#pragma unroll
        for (int p = 0; p < 2; p++) {
            int idx = p * 512 + t;
            int row = idx >> 5, seg = idx & 31;
            cp_async16(sW + buf * SW_BUF + row * SW_STRIDE + seg * 4,
                       W + (size_t)(chunk * 32 + row) * 128 + seg * 4);
        }
        cp_commit();
    };
    auto stage_tail = [&](int buf) {
        // action: 256 rows x 16 floats
#pragma unroll
        for (int p = 0; p < 2; p++) {
            int idx = p * 512 + t;
            int row = idx >> 2, seg = idx & 3;
            int g = rb + row; if (g >= N_NODES) g = N_NODES - 1;
            cp_async16(sA + buf * SA_BUF + row * SA_STRIDE + seg * 4,
                       act + (size_t)g * 16 + seg * 4);
        }
        // W rows 128..143 x 128
        {
            int row = t >> 5, seg = t & 31;
            cp_async16(sW + buf * SW_BUF + row * SW_STRIDE + seg * 4,
                       W + (size_t)(128 + row) * 128 + seg * 4);
        }
        cp_commit();
    };

    const int lane = t & 31;
    const int warp = t >> 5;
    const int m0w = (warp >> 1) * 32;
    const int c0w = (warp & 1) * 64;
    const int qid = lane >> 2;
    const int t4 = lane & 3;

    float d[2][8][4];
#pragma unroll
    for (int mt = 0; mt < 2; mt++)
#pragma unroll
        for (int nt = 0; nt < 8; nt++)
#pragma unroll
            for (int i = 0; i < 4; i++) d[mt][nt][i] = 0.f;

    stage_main(0, 0);

#pragma unroll
    for (int c = 0; c < 5; c++) {
        if (c < 4) {
            if (c + 1 < 4) stage_main(c + 1, (c + 1) & 1);
            else stage_tail((c + 1) & 1);
            cp_wait<1>();
        } else {
            cp_wait<0>();
        }
        __syncthreads();

        const unsigned* cA = (const unsigned*)(sA + (c & 1) * SA_BUF);
        const unsigned* cW = (const unsigned*)(sW + (c & 1) * SW_BUF);
        const int iters = (c < 4) ? 4 : 2;
#pragma unroll
        for (int it = 0; it < 4; it++) {
            if (it >= iters) break;
            const int k = it * 8;
            unsigned a[2][4];
#pragma unroll
            for (int mt = 0; mt < 2; mt++) {
                const int base = (m0w + mt * 16 + qid) * SA_STRIDE + k + t4;
                a[mt][0] = cA[base];
                a[mt][1] = cA[base + 8 * SA_STRIDE];
                a[mt][2] = cA[base + 4];
                a[mt][3] = cA[base + 8 * SA_STRIDE + 4];
            }
#pragma unroll
            for (int nt = 0; nt < 8; nt++) {
                const int wb = (k + t4) * SW_STRIDE + c0w + nt * 8 + qid;
                unsigned b0 = cW[wb];
                unsigned b1 = cW[wb + 4 * SW_STRIDE];
                mma_tf32(d[0][nt][0], d[0][nt][1], d[0][nt][2], d[0][nt][3],
                         a[0][0], a[0][1], a[0][2], a[0][3], b0, b1);
                mma_tf32(d[1][nt][0], d[1][nt][1], d[1][nt][2], d[1][nt][3],
                         a[1][0], a[1][1], a[1][2], a[1][3], b0, b1);
            }
        }
        __syncthreads();
    }

    // epilogue: relu(+bias) . fc2 over this warp's 64 cols
    float p[2][2];
    p[0][0] = p[0][1] = p[1][0] = p[1][1] = 0.f;
#pragma unroll
    for (int mt = 0; mt < 2; mt++)
#pragma unroll
        for (int nt = 0; nt < 8; nt++) {
            const int col = c0w + nt * 8 + t4 * 2;
            float2 bv = *(const float2*)(bias + col);
            float2 wv = *(const float2*)(w2 + col);
            p[mt][0] += fmaxf(d[mt][nt][0] + bv.x, 0.f) * wv.x
                      + fmaxf(d[mt][nt][1] + bv.y, 0.f) * wv.y;
            p[mt][1] += fmaxf(d[mt][nt][2] + bv.x, 0.f) * wv.x
                      + fmaxf(d[mt][nt][3] + bv.y, 0.f) * wv.y;
        }
#pragma unroll
    for (int mt = 0; mt < 2; mt++)
#pragma unroll
        for (int h = 0; h < 2; h++) {
            p[mt][h] += __shfl_xor_sync(0xFFFFFFFFu, p[mt][h], 1);
            p[mt][h] += __shfl_xor_sync(0xFFFFFFFFu, p[mt][h], 2);
        }

    // cross-warp-pair combine via smem scratch (reuse sA buffer 0; safe after barrier)
    float* scr = smem_f;   // 256 floats
    if (c0w == 0 && t4 == 0) {
#pragma unroll
        for (int mt = 0; mt < 2; mt++) {
            scr[m0w + mt * 16 + qid] = p[mt][0];
            scr[m0w + mt * 16 + qid + 8] = p[mt][1];
        }
    }
    __syncthreads();
    if (c0w == 64 && t4 == 0) {
        const float ob = __ldg(w2b);
#pragma unroll
        for (int mt = 0; mt < 2; mt++) {
            int lr = m0w + mt * 16 + qid;
            int grow = rb + lr;
            if (grow < N_NODES) out[grow] = p[mt][0] + scr[lr] + ob;
            if (grow + 8 < N_NODES) out[grow + 8] = p[mt][1] + scr[lr + 8] + ob;
        }
    }
}

// ---------------- gather-aggregate: one warp per dst row (fp16 y) -----------
__global__ void __launch_bounds__(256) k_aggregate(
    const float* __restrict__ bias)
{
    const int lane = threadIdx.x & 31;
    const int warp = threadIdx.x >> 5;
    const int row = blockIdx.x * 8 + warp;
    if (row >= N_NODES) return;

    const int s = g_rowptr[row];
    const int e = g_rowptr[row + 1];
    const uint2* yv = (const uint2*)g_y16;

    float4 a0, a1, a2, a3;
    {
        uint2 u = __ldg(&yv[(size_t)row * 32 + lane]);
        float2 f0 = __half22float2(*(__half2*)&u.x);
        float2 f1 = __half22float2(*(__half2*)&u.y);
        a0 = make_float4(f0.x, f0.y, f1.x, f1.y);
    }
    a1 = make_float4(0.f, 0.f, 0.f, 0.f);
    a2 = a1; a3 = a1;

    int i = s;
    for (; i + 4 <= e; i += 4) {
        int i0 = g_csr[i + 0];
        int i1 = g_csr[i + 1];
        int i2 = g_csr[i + 2];
        int i3 = g_csr[i + 3];
        uint2 u0 = __ldg(&yv[(size_t)i0 * 32 + lane]);
        uint2 u1 = __ldg(&yv[(size_t)i1 * 32 + lane]);
        uint2 u2 = __ldg(&yv[(size_t)i2 * 32 + lane]);
        uint2 u3 = __ldg(&yv[(size_t)i3 * 32 + lane]);
        float2 f;
        f = __half22float2(*(__half2*)&u0.x); a0.x += f.x; a0.y += f.y;
        f = __half22float2(*(__half2*)&u0.y); a0.z += f.x; a0.w += f.y;
        f = __half22float2(*(__half2*)&u1.x); a1.x += f.x; a1.y += f.y;
        f = __half22float2(*(__half2*)&u1.y); a1.z += f.x; a1.w += f.y;
        f = __half22float2(*(__half2*)&u2.x); a2.x += f.x; a2.y += f.y;
        f = __half22float2(*(__half2*)&u2.y); a2.z += f.x; a2.w += f.y;
        f = __half22float2(*(__half2*)&u3.x); a3.x += f.x; a3.y += f.y;
        f = __half22float2(*(__half2*)&u3.y); a3.z += f.x; a3.w += f.y;
    }
    for (; i < e; i++) {
        int ix = g_csr[i];
        uint2 u = __ldg(&yv[(size_t)ix * 32 + lane]);
        float2 f;
        f = __half22float2(*(__half2*)&u.x); a0.x += f.x; a0.y += f.y;
        f = __half22float2(*(__half2*)&u.y); a0.z += f.x; a0.w += f.y;
    }
    float4 a = make_float4(a0.x + a1.x + a2.x + a3.x,
                           a0.y + a1.y + a2.y + a3.y,
                           a0.z + a1.z + a2.z + a3.z,
                           a0.w + a1.w + a2.w + a3.w);

    const float dv = g_dinv[row];
    float4 b4 = __ldg((const float4*)(bias + lane * 4));
    float4 o = make_float4(fmaxf(a.x * dv + b4.x, 0.f),
                           fmaxf(a.y * dv + b4.y, 0.f),
                           fmaxf(a.z * dv + b4.z, 0.f),
                           fmaxf(a.w * dv + b4.w, 0.f));
    *(float4*)(g_h + (size_t)row * 128 + lane * 4) = o;
}

// ---------------- launch ----------------------------------------------------
extern "C" void kernel_launch(void* const* d_in, const int* in_sizes, int n_in,
                              void* d_out, int out_size)
{
    const float* x      = (const float*)d_in[0];
    const int*   ei     = (const int*)d_in[1];
    const float* action = (const float*)d_in[2];
    const float* g1w    = (const float*)d_in[3];
    const float* g1b    = (const float*)d_in[4];
    const float* g2w    = (const float*)d_in[5];
    const float* g2b    = (const float*)d_in[6];
    const float* f1w    = (const float*)d_in[7];
    const float* f1b    = (const float*)d_in[8];
    const float* f2w    = (const float*)d_in[9];
    const float* f2b    = (const float*)d_in[10];
    float*       q      = (float*)d_out;

    cudaFuncSetAttribute(k_gemm_cp<0>, cudaFuncAttributeMaxDynamicSharedMemorySize, GEMM_SMEM);
    cudaFuncSetAttribute(k_gemm_cp<1>, cudaFuncAttributeMaxDynamicSharedMemorySize, GEMM_SMEM);
    cudaFuncSetAttribute(k_fc_cp,      cudaFuncAttributeMaxDynamicSharedMemorySize, GEMM_SMEM);

    const int agg_grid = (N_NODES + 7) / 8;

    // CSR build (gemm1 kept at slot 3 for the ncu window)
    k_detect_init<<<SCAN_BLOCKS, 1024>>>(ei);                       // 0
    k_hist<<<(N_EDGES + 255) / 256, 256>>>(ei);                     // 1
    k_scan<<<SCAN_BLOCKS, 1024>>>();                                // 2
    k_gemm_cp<0><<<GEMM_BLOCKS, 512, GEMM_SMEM>>>(x, g1w);          // 3  <- profiled
    k_fill<<<(N_EDGES + 255) / 256, 256>>>(ei);                     // 4

    k_aggregate<<<agg_grid, 256>>>(g1b);                            // 5

    k_gemm_cp<1><<<GEMM_BLOCKS, 512, GEMM_SMEM>>>(nullptr, g2w);    // 6
    k_aggregate<<<agg_grid, 256>>>(g2b);                            // 7

    k_fc_cp<<<GEMM_BLOCKS, 512, GEMM_SMEM>>>(action, f1w, f1b, f2w, f2b, q);  // 8
}